// round 12
// baseline (speedup 1.0000x reference)
#include <cuda_runtime.h>
#include <cuda_fp16.h>
#include <cstdint>

// ---------------- constants ----------------
#define BATCH   2
#define NSEQ    2048
#define DIMM    4096
#define NHEAD   32
#define NKV     8
#define HDIM    128
#define MROWS   (BATCH*NSEQ)            // 4096
#define KVDIM   (NKV*HDIM)              // 1024
#define ATT_SCALE 0.08838834764831845f  // 1/sqrt(128)

// ---------------- scratch (device globals; no allocations allowed) ----------------
__device__ __half g_x16h[MROWS * DIMM], g_x16l[MROWS * DIMM];
__device__ __half g_wq16[DIMM * DIMM];
__device__ __half g_wk16[KVDIM * DIMM];
__device__ __half g_wv16[KVDIM * DIMM];
__device__ __half g_wo16[DIMM * DIMM];

__device__ __half g_q16h[MROWS * DIMM], g_q16l[MROWS * DIMM];  // roped+scaled Q hi/lo
__device__ __half g_k16[MROWS * KVDIM];                        // roped K
__device__ __half g_v16[MROWS * KVDIM];
__device__ __half g_o16[MROWS * DIMM];

// ---------------- PTX helpers (plain sm_80+ PTX) ----------------
__device__ __forceinline__ uint32_t s2u32(const void* p) {
    uint32_t a;
    asm("{ .reg .u64 t; cvta.to.shared.u64 t, %1; cvt.u32.u64 %0, t; }" : "=r"(a) : "l"(p));
    return a;
}
__device__ __forceinline__ void cp16(uint32_t d, const void* s) {
    asm volatile("cp.async.cg.shared.global [%0], [%1], 16;" :: "r"(d), "l"(s));
}
__device__ __forceinline__ void cp_commit() {
    asm volatile("cp.async.commit_group;" ::: "memory");
}
template <int N>
__device__ __forceinline__ void cp_wait() {
    asm volatile("cp.async.wait_group %0;" :: "n"(N) : "memory");
}
__device__ __forceinline__ void ldsm4(uint32_t& r0, uint32_t& r1, uint32_t& r2,
                                      uint32_t& r3, uint32_t addr) {
    asm volatile("ldmatrix.sync.aligned.m8n8.x4.shared.b16 {%0,%1,%2,%3}, [%4];"
                 : "=r"(r0), "=r"(r1), "=r"(r2), "=r"(r3) : "r"(addr));
}
__device__ __forceinline__ void ldsm4t(uint32_t& r0, uint32_t& r1, uint32_t& r2,
                                       uint32_t& r3, uint32_t addr) {
    asm volatile("ldmatrix.sync.aligned.m8n8.x4.trans.shared.b16 {%0,%1,%2,%3}, [%4];"
                 : "=r"(r0), "=r"(r1), "=r"(r2), "=r"(r3) : "r"(addr));
}
__device__ __forceinline__ void mma16816f(float* c, const uint32_t* a, uint32_t b0, uint32_t b1) {
    asm volatile(
        "mma.sync.aligned.m16n8k16.row.col.f32.f16.f16.f32 "
        "{%0,%1,%2,%3}, {%4,%5,%6,%7}, {%8,%9}, {%0,%1,%2,%3};"
        : "+f"(c[0]), "+f"(c[1]), "+f"(c[2]), "+f"(c[3])
        : "r"(a[0]), "r"(a[1]), "r"(a[2]), "r"(a[3]), "r"(b0), "r"(b1));
}
__device__ __forceinline__ uint32_t packh2(float x, float y) {
    __half2 h = __floats2half2_rn(x, y);
    return *(uint32_t*)&h;
}

// ---------------- hi/lo split: fp32 -> fp16 pair ----------------
__global__ __launch_bounds__(256) void splitf16_kernel(
    const float* __restrict__ src, __half* __restrict__ hi,
    __half* __restrict__ lo, int n4)
{
    int i = blockIdx.x * blockDim.x + threadIdx.x;
    if (i >= n4) return;
    float4 v = ((const float4*)src)[i];
    __half h0 = __float2half_rn(v.x), h1 = __float2half_rn(v.y);
    __half h2 = __float2half_rn(v.z), h3 = __float2half_rn(v.w);
    __half l0 = __float2half_rn(v.x - __half2float(h0));
    __half l1 = __float2half_rn(v.y - __half2float(h1));
    __half l2 = __float2half_rn(v.z - __half2float(h2));
    __half l3 = __float2half_rn(v.w - __half2float(h3));
    ((__half2*)hi)[2 * i]     = __halves2half2(h0, h1);
    ((__half2*)hi)[2 * i + 1] = __halves2half2(h2, h3);
    ((__half2*)lo)[2 * i]     = __halves2half2(l0, l1);
    ((__half2*)lo)[2 * i + 1] = __halves2half2(l2, l3);
}

// ---------------- fp32 -> fp16 convert ----------------
__global__ __launch_bounds__(256) void cvt16_kernel(
    const float* __restrict__ src, __half* __restrict__ dst, int n4)
{
    int i = blockIdx.x * blockDim.x + threadIdx.x;
    if (i >= n4) return;
    float4 v = ((const float4*)src)[i];
    ((__half2*)dst)[2 * i]     = __floats2half2_rn(v.x, v.y);
    ((__half2*)dst)[2 * i + 1] = __floats2half2_rn(v.z, v.w);
}

// =====================================================================
// GEMMs: C[M,N] = A[M,K] * B[N,K]^T, fp16 in, fp32 accum, BK=64,
// 3-stage cp.async, single __syncthreads per iteration, pitch 144B.
// =====================================================================
#define TILE144  (128 * 144)         // 128x64-fp16 tile
#define TILE144B (256 * 144)         // 256x64-fp16 tile

// fused epilogues (row block of 2x16 rows handled per mt step):
//  EPI 0: rope + ATT_SCALE + hi/lo fp16 split -> Ch, Cl   (Q)
//  EPI 1: rope + fp16 -> Ch                                (K)
//  EPI 2: fp16 -> Ch                                       (V)
template <int EPI>
__device__ __forceinline__ void epi_store(
    float* p, __half* Ch, __half* Cl,
    const float* cosb, const float* sinb,
    int r0, int n0, int c0, int N)
{
    float p0 = p[0], p1 = p[1], p2 = p[2], p3 = p[3];
    if (EPI <= 1) {
        int j = (c0 & (HDIM - 1)) >> 1;
        float ca = cosb[n0 * 64 + j],       sa = sinb[n0 * 64 + j];
        float cb = cosb[(n0 + 8) * 64 + j], sb = sinb[(n0 + 8) * 64 + j];
        float t0 = p0 * ca - p1 * sa, t1 = p0 * sa + p1 * ca;
        float t2 = p2 * cb - p3 * sb, t3 = p2 * sb + p3 * cb;
        p0 = t0; p1 = t1; p2 = t2; p3 = t3;
    }
    if (EPI == 0) {
        p0 *= ATT_SCALE; p1 *= ATT_SCALE; p2 *= ATT_SCALE; p3 *= ATT_SCALE;
        __half h0 = __float2half_rn(p0), h1 = __float2half_rn(p1);
        __half h2 = __float2half_rn(p2), h3 = __float2half_rn(p3);
        *(__half2*)&Ch[(size_t)r0 * N + c0]       = __halves2half2(h0, h1);
        *(__half2*)&Ch[(size_t)(r0 + 8) * N + c0] = __halves2half2(h2, h3);
        *(__half2*)&Cl[(size_t)r0 * N + c0] = __halves2half2(
            __float2half_rn(p0 - __half2float(h0)),
            __float2half_rn(p1 - __half2float(h1)));
        *(__half2*)&Cl[(size_t)(r0 + 8) * N + c0] = __halves2half2(
            __float2half_rn(p2 - __half2float(h2)),
            __float2half_rn(p3 - __half2float(h3)));
    } else {
        *(__half2*)&Ch[(size_t)r0 * N + c0]       = __floats2half2_rn(p0, p1);
        *(__half2*)&Ch[(size_t)(r0 + 8) * N + c0] = __floats2half2_rn(p2, p3);
    }
}

// ---------------- 2-pass (A hi/lo, B single), CTA 128x128: K projection ----------------
#define G2STAGE (3 * TILE144)        // 55296
#define G2SMEM  (3 * G2STAGE)        // 165888
template <int EPI>
__global__ __launch_bounds__(256) void gemm2p(
    const __half* __restrict__ Ah, const __half* __restrict__ Al,
    const __half* __restrict__ B, __half* __restrict__ Ch, __half* __restrict__ Cl,
    const float* __restrict__ cosb, const float* __restrict__ sinb, int N, int K)
{
    extern __shared__ char smraw[];
    const uint32_t sbase = s2u32(smraw);
    const int tid  = threadIdx.x;
    const int wid  = tid >> 5;
    const int lane = tid & 31;
    const int bm = blockIdx.y << 7, bn = blockIdx.x << 7;
    const int wm = (wid & 3) * 32;
    const int wn = (wid >> 2) * 64;
    const int NCH = K >> 6;

    float acc[2][8][4];
#pragma unroll
    for (int i = 0; i < 2; i++)
#pragma unroll
        for (int j = 0; j < 8; j++)
#pragma unroll
            for (int t = 0; t < 4; t++) acc[i][j][t] = 0.0f;

    const __half* tsrc[3] = {Ah, Al, B};

    auto load_stage = [&](int ch, int st) {
        const int k0 = ch << 6;
        const uint32_t stb = sbase + st * G2STAGE;
#pragma unroll
        for (int i = 0; i < 12; i++) {
            int f = i * 256 + tid;
            int tile = f >> 10;
            int c = f & 1023;
            int row = c >> 3, ch8 = c & 7;
            const __half* g = tsrc[tile];
            int rb = (tile < 2) ? bm : bn;
            cp16(stb + tile * TILE144 + row * 144 + ch8 * 16,
                 g + (size_t)(rb + row) * K + k0 + ch8 * 8);
        }
    };

    uint32_t offA[2], offB[4];
#pragma unroll
    for (int mt = 0; mt < 2; mt++)
        offA[mt] = (uint32_t)((wm + mt * 16 + (lane & 15)) * 144 + (lane >> 4) * 16);
#pragma unroll
    for (int nb = 0; nb < 4; nb++)
        offB[nb] = (uint32_t)((wn + nb * 16 + (lane & 15)) * 144 + (lane >> 4) * 16);

    load_stage(0, 0); cp_commit();
    load_stage(1, 1); cp_commit();

    for (int it = 0; it < NCH; ++it) {
        if (it + 1 < NCH) cp_wait<1>(); else cp_wait<0>();
        __syncthreads();
        if (it + 2 < NCH) { load_stage(it + 2, (it + 2) % 3); cp_commit(); }

        const uint32_t bAh = sbase + (it % 3) * G2STAGE;
        const uint32_t bAl = bAh + TILE144;
        const uint32_t bB  = bAh + 2 * TILE144;

#pragma unroll
        for (int kk = 0; kk < 4; kk++) {
            const uint32_t ks = kk * 32;
            uint32_t ah[2][4], al[2][4], bfr[4][4];
#pragma unroll
            for (int mt = 0; mt < 2; mt++) {
                ldsm4(ah[mt][0], ah[mt][1], ah[mt][2], ah[mt][3], bAh + offA[mt] + ks);
                ldsm4(al[mt][0], al[mt][1], al[mt][2], al[mt][3], bAl + offA[mt] + ks);
            }
#pragma unroll
            for (int nb = 0; nb < 4; nb++)
                ldsm4(bfr[nb][0], bfr[nb][1], bfr[nb][2], bfr[nb][3], bB + offB[nb] + ks);
#pragma unroll
            for (int mt = 0; mt < 2; mt++)
#pragma unroll
                for (int nb = 0; nb < 4; nb++)
#pragma unroll
                    for (int hf = 0; hf < 2; hf++) {
                        float* c = acc[mt][nb * 2 + hf];
                        mma16816f(c, ah[mt], bfr[nb][hf], bfr[nb][hf + 2]);
                        mma16816f(c, al[mt], bfr[nb][hf], bfr[nb][hf + 2]);
                    }
        }
    }

#pragma unroll
    for (int mt = 0; mt < 2; mt++) {
        int r0 = bm + wm + mt * 16 + (lane >> 2);
        int n0 = r0 & (NSEQ - 1);
#pragma unroll
        for (int nt = 0; nt < 8; nt++) {
            int c0 = bn + wn + nt * 8 + (lane & 3) * 2;
            epi_store<EPI>(acc[mt][nt], Ch, Cl, cosb, sinb, r0, n0, c0, N);
        }
    }
}

// ---------------- 1-pass, CTA 128x256 (warp tile 64x64): Q / V / O ----------------
// EPI 0/2 -> fp16 epilogue; EPI 3 -> fp32 plain store (O projection).
#define G1STAGE (TILE144 + TILE144B)   // 55296
#define G1SMEM  (3 * G1STAGE)          // 165888
template <int EPI, typename OUTT>
__global__ __launch_bounds__(256) void gemm1p256(
    const __half* __restrict__ A, const __half* __restrict__ B,
    OUTT* __restrict__ Ch, __half* __restrict__ Cl,
    const float* __restrict__ cosb, const float* __restrict__ sinb, int N, int K)
{
    extern __shared__ char smraw[];
    const uint32_t sbase = s2u32(smraw);
    const int tid  = threadIdx.x;
    const int wid  = tid >> 5;
    const int lane = tid & 31;
    const int bm = blockIdx.y << 7, bn = blockIdx.x << 8;
    const int wm = (wid >> 2) * 64;          // 0 or 64
    const int wn = (wid & 3) * 64;           // 0..192
    const int NCH = K >> 6;

    float acc[4][8][4];
#pragma unroll
    for (int i = 0; i < 4; i++)
#pragma unroll
        for (int j = 0; j < 8; j++)
#pragma unroll
            for (int t = 0; t < 4; t++) acc[i][j][t] = 0.0f;

    auto load_stage = [&](int ch, int st) {
        const int k0 = ch << 6;
        const uint32_t stb = sbase + st * G1STAGE;
#pragma unroll
        for (int i = 0; i < 12; i++) {
            int f = i * 256 + tid;               // 0..3071
            if (f < 1024) {                       // A tile: 128 rows
                int row = f >> 3, ch8 = f & 7;
                cp16(stb + row * 144 + ch8 * 16,
                     A + (size_t)(bm + row) * K + k0 + ch8 * 8);
            } else {                              // B tile: 256 rows
                int c = f - 1024;
                int row = c >> 3, ch8 = c & 7;
                cp16(stb + TILE144 + row * 144 + ch8 * 16,
                     B + (size_t)(bn + row) * K + k0 + ch8 * 8);
            }
        }
    };

    uint32_t offA[4], offB[4];
#pragma unroll
    for (int mt = 0; mt < 4; mt++)
        offA[mt] = (uint32_t)((wm + mt * 16 + (lane & 15)) * 144 + (lane >> 4) * 16);
#pragma unroll
    for (int nb = 0; nb < 4; nb++)
        offB[nb] = (uint32_t)((wn + nb * 16 + (lane & 15)) * 144 + (lane >> 4) * 16);

    load_stage(0, 0); cp_commit();
    load_stage(1, 1); cp_commit();

    for (int it = 0; it < NCH; ++it) {
        if (it + 1 < NCH) cp_wait<1>(); else cp_wait<0>();
        __syncthreads();
        if (it + 2 < NCH) { load_stage(it + 2, (it + 2) % 3); cp_commit(); }

        const uint32_t bA = sbase + (it % 3) * G1STAGE;
        const uint32_t bB = bA + TILE144;

#pragma unroll
        for (int kk = 0; kk < 4; kk++) {
            const uint32_t ks = kk * 32;
            uint32_t a[4][4], bfr[4][4];
#pragma unroll
            for (int mt = 0; mt < 4; mt++)
                ldsm4(a[mt][0], a[mt][1], a[mt][2], a[mt][3], bA + offA[mt] + ks);
#pragma unroll
            for (int nb = 0; nb < 4; nb++)
                ldsm4(bfr[nb][0], bfr[nb][1], bfr[nb][2], bfr[nb][3], bB + offB[nb] + ks);
#pragma unroll
            for (int mt = 0; mt < 4; mt++)
#pragma unroll
                for (int nb = 0; nb < 4; nb++)
#pragma unroll
                    for (int hf = 0; hf < 2; hf++)
                        mma16816f(acc[mt][nb * 2 + hf], a[mt],
                                  bfr[nb][hf], bfr[nb][hf + 2]);
        }
    }

#pragma unroll
    for (int mt = 0; mt < 4; mt++) {
        int r0 = bm + wm + mt * 16 + (lane >> 2);
        int n0 = r0 & (NSEQ - 1);
#pragma unroll
        for (int nt = 0; nt < 8; nt++) {
            int c0 = bn + wn + nt * 8 + (lane & 3) * 2;
            float* p = acc[mt][nt];
            if constexpr (EPI == 3) {
                *(float2*)&Ch[(size_t)r0 * N + c0]       = make_float2(p[0], p[1]);
                *(float2*)&Ch[(size_t)(r0 + 8) * N + c0] = make_float2(p[2], p[3]);
            } else {
                epi_store<EPI>(p, (__half*)Ch, Cl, cosb, sinb, r0, n0, c0, N);
            }
        }
    }
}

// ---------------- flash attention via mma.sync (unchanged from R10) ----------------
#define APITCH  272
#define QS_BYTES (128 * APITCH)
#define KVTILE   (64 * APITCH)
#define STG      (2 * KVTILE)
#define ASMEM    (2 * QS_BYTES + 2 * STG)
__global__ __launch_bounds__(256) void attn_mma(
    const __half* __restrict__ Qh, const __half* __restrict__ Ql,
    const __half* __restrict__ Kk, const __half* __restrict__ V,
    __half* __restrict__ O16)
{
    extern __shared__ char smraw[];
    const uint32_t sb = s2u32(smraw);
    const uint32_t qh_s = sb;
    const uint32_t ql_s = sb + QS_BYTES;
    const uint32_t kvb  = sb + 2 * QS_BYTES;

    const int tid = threadIdx.x;
    const int wid = tid >> 5, lane = tid & 31;
    const int qt = gridDim.x - 1 - blockIdx.x;
    const int bh = blockIdx.y;
    const int b = bh >> 5, h = bh & 31;
    const int kvh = h >> 2;

    {
        const size_t qrow0 = (size_t)(b * NSEQ + qt * 128) * DIMM + h * HDIM;
#pragma unroll
        for (int i = 0; i < 16; i++) {
            int f = i * 256 + tid;
            int tile = f >> 11;
            int c = f & 2047;
            int row = c >> 4, ch = c & 15;
            const __half* src = (tile ? Ql : Qh) + qrow0 + (size_t)row * DIMM + ch * 8;
            cp16((tile ? ql_s : qh_s) + row * APITCH + ch * 16, src);
        }
    }

    auto load_kv = [&](int kt, int st) {
        const uint32_t stb = kvb + st * STG;
        const size_t row0 = (size_t)(b * NSEQ + kt * 64) * KVDIM + kvh * HDIM;
#pragma unroll
        for (int i = 0; i < 8; i++) {
            int f = i * 256 + tid;
            int tile = f >> 10;
            int c = f & 1023;
            int row = c >> 4, ch = c & 15;
            const __half* src = (tile ? V : Kk) + row0 + (size_t)row * KVDIM + ch * 8;
            cp16(stb + tile * KVTILE + row * APITCH + ch * 16, src);
        }
    };

    float o[16][4];
#pragma unroll
    for (int t = 0; t < 16; t++)
#pragma unroll
        for (int r = 0; r < 4; r++) o[t][r] = 0.0f;
    float m0 = -1e30f, m1 = -1e30f, l0 = 0.0f, l1 = 0.0f;

    const int NIT = 2 * qt + 2;
    load_kv(0, 0); cp_commit();

    const int rowA = qt * 128 + wid * 16 + (lane >> 2);
    const uint32_t aoff = (uint32_t)((wid * 16 + (lane & 15)) * APITCH + (lane >> 4) * 16);

    for (int it = 0; it < NIT; it++) {
        const int st = it & 1;
        cp_wait<0>();
        __syncthreads();
        if (it + 1 < NIT) { load_kv(it + 1, st ^ 1); cp_commit(); }

        const uint32_t k_t = kvb + st * STG;
        const uint32_t v_t = k_t + KVTILE;

        float s[8][4];
#pragma unroll
        for (int t = 0; t < 8; t++)
#pragma unroll
            for (int r = 0; r < 4; r++) s[t][r] = 0.0f;

#pragma unroll
        for (int kki = 0; kki < 8; kki++) {
            uint32_t ah[4], al[4];
            ldsm4(ah[0], ah[1], ah[2], ah[3], qh_s + aoff + kki * 32);
            ldsm4(al[0], al[1], al[2], al[3], ql_s + aoff + kki * 32);
#pragma unroll
            for (int g = 0; g < 4; g++) {
                uint32_t boff = (uint32_t)((16 * g + (lane & 15)) * APITCH
                                           + (kki * 2 + (lane >> 4)) * 16);
                uint32_t b0, b1, b2, b3;
                ldsm4(b0, b1, b2, b3, k_t + boff);
                mma16816f(s[2 * g],     ah, b0, b2);
                mma16816f(s[2 * g],     al, b0, b2);
                mma16816f(s[2 * g + 1], ah, b1, b3);
                mma16816f(s[2 * g + 1], al, b1, b3);
            }
        }

        if (it >= 2 * qt) {
            const int kbase = it * 64 + (lane & 3) * 2;
#pragma unroll
            for (int t = 0; t < 8; t++) {
                int k0 = kbase + t * 8;
                if (k0     > rowA)     s[t][0] = -1e30f;
                if (k0 + 1 > rowA)     s[t][1] = -1e30f;
                if (k0     > rowA + 8) s[t][2] = -1e30f;
                if (k0 + 1 > rowA + 8) s[t][3] = -1e30f;
            }
        }

        float mxA = m0, mxB = m1;
#pragma unroll
        for (int t = 0; t < 8; t++) {
            mxA = fmaxf(mxA, fmaxf(s[t][0], s[t][1]));
            mxB = fmaxf(mxB, fmaxf(s[t][2], s[t][3]));
        }
        mxA = fmaxf(mxA, __shfl_xor_sync(0xFFFFFFFFu, mxA, 1));
        mxA = fmaxf(mxA, __shfl_xor_sync(0xFFFFFFFFu, mxA, 2));
        mxB = fmaxf(mxB, __shfl_xor_sync(0xFFFFFFFFu, mxB, 1));
        mxB = fmaxf(mxB, __shfl_xor_sync(0xFFFFFFFFu, mxB, 2));

        float aA = __expf(m0 - mxA), aB = __expf(m1 - mxB);
        float sA = 0.0f, sB = 0.0f;
#pragma unroll
        for (int t = 0; t < 8; t++) {
            s[t][0] = __expf(s[t][0] - mxA);
            s[t][1] = __expf(s[t][1] - mxA);
            s[t][2] = __expf(s[t][2] - mxB);
            s[t][3] = __expf(s[t][3] - mxB);
            sA += s[t][0] + s[t][1];
            sB += s[t][2] + s[t][3];
        }
        sA += __shfl_xor_sync(0xFFFFFFFFu, sA, 1);
        sA += __shfl_xor_sync(0xFFFFFFFFu, sA, 2);
        sB += __shfl_xor_sync(0xFFFFFFFFu, sB, 1);
        sB += __shfl_xor_sync(0xFFFFFFFFu, sB, 2);
        l0 = l0 * aA + sA;  l1 = l1 * aB + sB;
        m0 = mxA;           m1 = mxB;

#pragma unroll
        for (int t = 0; t < 16; t++) {
            o[t][0] *= aA; o[t][1] *= aA;
            o[t][2] *= aB; o[t][3] *= aB;
        }

        uint32_t ap[4][4];
#pragma unroll
        for (int kk = 0; kk < 4; kk++) {
            ap[kk][0] = packh2(s[2 * kk][0],     s[2 * kk][1]);
            ap[kk][1] = packh2(s[2 * kk][2],     s[2 * kk][3]);
            ap[kk][2] = packh2(s[2 * kk + 1][0], s[2 * kk + 1][1]);
            ap[kk][3] = packh2(s[2 * kk + 1][2], s[2 * kk + 1][3]);
        }
        const uint32_t vrow = (uint32_t)((((lane >> 3) & 1) * 8 + (lane & 7)) * APITCH
                                         + (lane >> 4) * 16);
#pragma unroll
        for (int kk = 0; kk < 4; kk++) {
#pragma unroll
            for (int g = 0; g < 8; g++) {
                uint32_t v0, v1, v2, v3;
                ldsm4t(v0, v1, v2, v3, v_t + vrow + (uint32_t)(16 * kk * APITCH + g * 32));
                mma16816f(o[2 * g],     ap[kk], v0, v1);
                mma16816f(o[2 * g + 1], ap[kk], v2, v3);
            }
        }
    }

    const float iA = 1.0f / l0, iB = 1.0f / l1;
    __half* obase = O16 + ((size_t)(b * NSEQ) * NHEAD + h) * HDIM;
#pragma unroll
    for (int t = 0; t < 16; t++) {
        int d = t * 8 + (lane & 3) * 2;
        *(__half2*)(obase + (size_t)rowA * (NHEAD * HDIM) + d) =
            __floats2half2_rn(o[t][0] * iA, o[t][1] * iA);
        *(__half2*)(obase + (size_t)(rowA + 8) * (NHEAD * HDIM) + d) =
            __floats2half2_rn(o[t][2] * iB, o[t][3] * iB);
    }
}

// ---------------- launch ----------------
extern "C" void kernel_launch(void* const* d_in, const int* in_sizes, int n_in,
                              void* d_out, int out_size)
{
    const float* x    = (const float*)d_in[0];
    const float* wq   = (const float*)d_in[1];
    const float* wk   = (const float*)d_in[2];
    const float* wv   = (const float*)d_in[3];
    const float* wo   = (const float*)d_in[4];
    const float* cosb = (const float*)d_in[5];
    const float* sinb = (const float*)d_in[6];
    float* out = (float*)d_out;

    __half *x16h, *x16l, *wq16, *wk16, *wv16, *wo16;
    cudaGetSymbolAddress((void**)&x16h, g_x16h);
    cudaGetSymbolAddress((void**)&x16l, g_x16l);
    cudaGetSymbolAddress((void**)&wq16, g_wq16);
    cudaGetSymbolAddress((void**)&wk16, g_wk16);
    cudaGetSymbolAddress((void**)&wv16, g_wv16);
    cudaGetSymbolAddress((void**)&wo16, g_wo16);
    __half *q16h, *q16l, *k16, *v16, *o16;
    cudaGetSymbolAddress((void**)&q16h, g_q16h);
    cudaGetSymbolAddress((void**)&q16l, g_q16l);
    cudaGetSymbolAddress((void**)&k16,  g_k16);
    cudaGetSymbolAddress((void**)&v16,  g_v16);
    cudaGetSymbolAddress((void**)&o16,  g_o16);

    cudaFuncSetAttribute(gemm2p<1>, cudaFuncAttributeMaxDynamicSharedMemorySize, G2SMEM);
    cudaFuncSetAttribute((const void*)gemm1p256<0, __half>,
                         cudaFuncAttributeMaxDynamicSharedMemorySize, G1SMEM);
    cudaFuncSetAttribute((const void*)gemm1p256<2, __half>,
                         cudaFuncAttributeMaxDynamicSharedMemorySize, G1SMEM);
    cudaFuncSetAttribute((const void*)gemm1p256<3, float>,
                         cudaFuncAttributeMaxDynamicSharedMemorySize, G1SMEM);
    cudaFuncSetAttribute(attn_mma, cudaFuncAttributeMaxDynamicSharedMemorySize, ASMEM);

    dim3 blk(256);

    // input conversions (x split feeds K 2-pass; hi used by 1-pass Q/V)
    splitf16_kernel<<<(MROWS * DIMM / 4 + 255) / 256, blk>>>(x, x16h, x16l, MROWS * DIMM / 4);
    cvt16_kernel<<<(DIMM * DIMM / 4 + 255) / 256, blk>>>(wq, wq16, DIMM * DIMM / 4);
    cvt16_kernel<<<(KVDIM * DIMM / 4 + 255) / 256, blk>>>(wk, wk16, KVDIM * DIMM / 4);
    cvt16_kernel<<<(KVDIM * DIMM / 4 + 255) / 256, blk>>>(wv, wv16, KVDIM * DIMM / 4);
    cvt16_kernel<<<(DIMM * DIMM / 4 + 255) / 256, blk>>>(wo, wo16, DIMM * DIMM / 4);

    // projections: Q 1-pass (rope+scale+hi/lo), K 2-pass (rope), V 1-pass
    gemm1p256<0, __half><<<dim3(DIMM / 256, MROWS / 128), blk, G1SMEM>>>(
        x16h, wq16, q16h, q16l, cosb, sinb, DIMM, DIMM);
    gemm2p<1><<<dim3(KVDIM / 128, MROWS / 128), blk, G2SMEM>>>(
        x16h, x16l, wk16, k16, nullptr, cosb, sinb, KVDIM, DIMM);
    gemm1p256<2, __half><<<dim3(KVDIM / 256, MROWS / 128), blk, G1SMEM>>>(
        x16h, wv16, v16, nullptr, cosb, sinb, KVDIM, DIMM);

    // attention (Q hi/lo, K/V fp16) -> fp16 o16
    attn_mma<<<dim3(NSEQ / 128, BATCH * NHEAD), blk, ASMEM>>>(q16h, q16l, k16, v16, o16);

    // output projection: single-pass fp16, fp32 out
    gemm1p256<3, float><<<dim3(DIMM / 256, MROWS / 128), blk, G1SMEM>>>(
        o16, wo16, out, nullptr, cosb, sinb, DIMM, DIMM);
}

// round 15
// speedup vs baseline: 1.0992x; 1.0992x over previous
#include <cuda_runtime.h>
#include <cuda_fp16.h>
#include <cstdint>

// ---------------- constants ----------------
#define BATCH   2
#define NSEQ    2048
#define DIMM    4096
#define NHEAD   32
#define NKV     8
#define HDIM    128
#define MROWS   (BATCH*NSEQ)            // 4096
#define KVDIM   (NKV*HDIM)              // 1024
#define ATT_SCALE 0.08838834764831845f  // 1/sqrt(128)

// ---------------- scratch (device globals; no allocations allowed) ----------------
__device__ __half g_x16[MROWS * DIMM];
__device__ __half g_wq16[DIMM * DIMM];
__device__ __half g_wk16[KVDIM * DIMM];
__device__ __half g_wv16[KVDIM * DIMM];
__device__ __half g_wo16[DIMM * DIMM];

__device__ __half g_q16h[MROWS * DIMM], g_q16l[MROWS * DIMM];  // roped+scaled Q hi/lo
__device__ __half g_k16[MROWS * KVDIM];                        // roped K
__device__ __half g_v16[MROWS * KVDIM];
__device__ __half g_o16[MROWS * DIMM];

// ---------------- PTX helpers (plain sm_80+ PTX) ----------------
__device__ __forceinline__ uint32_t s2u32(const void* p) {
    uint32_t a;
    asm("{ .reg .u64 t; cvta.to.shared.u64 t, %1; cvt.u32.u64 %0, t; }" : "=r"(a) : "l"(p));
    return a;
}
__device__ __forceinline__ void cp16(uint32_t d, const void* s) {
    asm volatile("cp.async.cg.shared.global [%0], [%1], 16;" :: "r"(d), "l"(s));
}
__device__ __forceinline__ void cp_commit() {
    asm volatile("cp.async.commit_group;" ::: "memory");
}
template <int N>
__device__ __forceinline__ void cp_wait() {
    asm volatile("cp.async.wait_group %0;" :: "n"(N) : "memory");
}
__device__ __forceinline__ void ldsm4(uint32_t& r0, uint32_t& r1, uint32_t& r2,
                                      uint32_t& r3, uint32_t addr) {
    asm volatile("ldmatrix.sync.aligned.m8n8.x4.shared.b16 {%0,%1,%2,%3}, [%4];"
                 : "=r"(r0), "=r"(r1), "=r"(r2), "=r"(r3) : "r"(addr));
}
__device__ __forceinline__ void ldsm4t(uint32_t& r0, uint32_t& r1, uint32_t& r2,
                                       uint32_t& r3, uint32_t addr) {
    asm volatile("ldmatrix.sync.aligned.m8n8.x4.trans.shared.b16 {%0,%1,%2,%3}, [%4];"
                 : "=r"(r0), "=r"(r1), "=r"(r2), "=r"(r3) : "r"(addr));
}
__device__ __forceinline__ void mma16816f(float* c, const uint32_t* a, uint32_t b0, uint32_t b1) {
    asm volatile(
        "mma.sync.aligned.m16n8k16.row.col.f32.f16.f16.f32 "
        "{%0,%1,%2,%3}, {%4,%5,%6,%7}, {%8,%9}, {%0,%1,%2,%3};"
        : "+f"(c[0]), "+f"(c[1]), "+f"(c[2]), "+f"(c[3])
        : "r"(a[0]), "r"(a[1]), "r"(a[2]), "r"(a[3]), "r"(b0), "r"(b1));
}
__device__ __forceinline__ uint32_t packh2(float x, float y) {
    __half2 h = __floats2half2_rn(x, y);
    return *(uint32_t*)&h;
}

// ---------------- fused fp32 -> fp16 conversion of all five tensors ----------------
#define C_X   (MROWS * DIMM / 4)              // 4,194,304 float4s
#define C_WQ  (DIMM * DIMM / 4)               // 4,194,304
#define C_WK  (KVDIM * DIMM / 4)              // 1,048,576
#define C_WV  (KVDIM * DIMM / 4)
#define C_WO  (DIMM * DIMM / 4)
#define C_TOT (C_X + C_WQ + C_WK + C_WV + C_WO)
__global__ __launch_bounds__(256) void cvt_all_kernel(
    const float* __restrict__ x,  const float* __restrict__ wq,
    const float* __restrict__ wk, const float* __restrict__ wv,
    const float* __restrict__ wo,
    __half* __restrict__ x16,  __half* __restrict__ wq16,
    __half* __restrict__ wk16, __half* __restrict__ wv16,
    __half* __restrict__ wo16)
{
    int i = blockIdx.x * blockDim.x + threadIdx.x;
    if (i >= C_TOT) return;
    const float* s; __half* d; int off;
    if (i < C_X)                        { s = x;  d = x16;  off = i; }
    else if (i < C_X + C_WQ)            { s = wq; d = wq16; off = i - C_X; }
    else if (i < C_X + C_WQ + C_WK)     { s = wk; d = wk16; off = i - C_X - C_WQ; }
    else if (i < C_X + C_WQ + C_WK + C_WV)
                                        { s = wv; d = wv16; off = i - C_X - C_WQ - C_WK; }
    else                                { s = wo; d = wo16; off = i - C_X - C_WQ - C_WK - C_WV; }
    float4 v = ((const float4*)s)[off];
    ((__half2*)d)[2 * off]     = __floats2half2_rn(v.x, v.y);
    ((__half2*)d)[2 * off + 1] = __floats2half2_rn(v.z, v.w);
}

// =====================================================================
// GEMM: C[M,N] = A[M,K] * B[N,K]^T, fp16 in, fp32 accum.
// CTA 128x128, BK=64, 256 thr (8 warps, warp tile 32x64), 3-stage cp.async,
// single __syncthreads per iteration, pitch 144B (conflict-free ldmatrix).
// =====================================================================
#define TILE144 (128 * 144)          // 18432 B: one 128x64-fp16 tile

// fused epilogues:
//  EPI 0: rope + ATT_SCALE + hi/lo fp16 split -> Ch, Cl   (Q)
//  EPI 1: rope + fp16 -> Ch                                (K)
//  EPI 2: fp16 -> Ch                                       (V)
template <int EPI>
__device__ __forceinline__ void epilogue16(
    float acc[2][8][4], __half* Ch, __half* Cl,
    const float* cosb, const float* sinb,
    int bm, int bn, int wm, int wn, int lane, int N)
{
#pragma unroll
    for (int mt = 0; mt < 2; mt++) {
        int r0 = bm + wm + mt * 16 + (lane >> 2);
        int n0 = r0 & (NSEQ - 1);
#pragma unroll
        for (int nt = 0; nt < 8; nt++) {
            int c0 = bn + wn + nt * 8 + (lane & 3) * 2;
            float* p = acc[mt][nt];
            float p0 = p[0], p1 = p[1], p2 = p[2], p3 = p[3];
            if (EPI <= 1) {
                int j = (c0 & (HDIM - 1)) >> 1;
                float ca = cosb[n0 * 64 + j],       sa = sinb[n0 * 64 + j];
                float cb = cosb[(n0 + 8) * 64 + j], sb = sinb[(n0 + 8) * 64 + j];
                float t0 = p0 * ca - p1 * sa, t1 = p0 * sa + p1 * ca;
                float t2 = p2 * cb - p3 * sb, t3 = p2 * sb + p3 * cb;
                p0 = t0; p1 = t1; p2 = t2; p3 = t3;
            }
            if (EPI == 0) {
                p0 *= ATT_SCALE; p1 *= ATT_SCALE; p2 *= ATT_SCALE; p3 *= ATT_SCALE;
                __half h0 = __float2half_rn(p0), h1 = __float2half_rn(p1);
                __half h2 = __float2half_rn(p2), h3 = __float2half_rn(p3);
                *(__half2*)&Ch[(size_t)r0 * N + c0]       = __halves2half2(h0, h1);
                *(__half2*)&Ch[(size_t)(r0 + 8) * N + c0] = __halves2half2(h2, h3);
                *(__half2*)&Cl[(size_t)r0 * N + c0] = __halves2half2(
                    __float2half_rn(p0 - __half2float(h0)),
                    __float2half_rn(p1 - __half2float(h1)));
                *(__half2*)&Cl[(size_t)(r0 + 8) * N + c0] = __halves2half2(
                    __float2half_rn(p2 - __half2float(h2)),
                    __float2half_rn(p3 - __half2float(h3)));
            } else {
                *(__half2*)&Ch[(size_t)r0 * N + c0]       = __floats2half2_rn(p0, p1);
                *(__half2*)&Ch[(size_t)(r0 + 8) * N + c0] = __floats2half2_rn(p2, p3);
            }
        }
    }
}

// ---------------- 1-pass with fused epilogue: Q / K / V projections ----------------
#define G1STAGE (2 * TILE144)        // 36864
#define G1SMEM  (3 * G1STAGE)        // 110592
template <int EPI>
__global__ __launch_bounds__(256) void gemm1pe(
    const __half* __restrict__ A, const __half* __restrict__ B,
    __half* __restrict__ Ch, __half* __restrict__ Cl,
    const float* __restrict__ cosb, const float* __restrict__ sinb, int N, int K)
{
    extern __shared__ char smraw[];
    const uint32_t sbase = s2u32(smraw);
    const int tid  = threadIdx.x;
    const int wid  = tid >> 5;
    const int lane = tid & 31;
    const int bm = blockIdx.y << 7, bn = blockIdx.x << 7;
    const int wm = (wid & 3) * 32;
    const int wn = (wid >> 2) * 64;
    const int NCH = K >> 6;

    float acc[2][8][4];
#pragma unroll
    for (int i = 0; i < 2; i++)
#pragma unroll
        for (int j = 0; j < 8; j++)
#pragma unroll
            for (int t = 0; t < 4; t++) acc[i][j][t] = 0.0f;

    auto load_stage = [&](int ch, int st) {
        const int k0 = ch << 6;
        const uint32_t stb = sbase + st * G1STAGE;
#pragma unroll
        for (int i = 0; i < 8; i++) {
            int f = i * 256 + tid;          // 0..2047 (2 tiles x 1024)
            int tile = f >> 10;
            int c = f & 1023;
            int row = c >> 3, ch8 = c & 7;
            const __half* g = tile ? B : A;
            int rb = tile ? bn : bm;
            cp16(stb + tile * TILE144 + row * 144 + ch8 * 16,
                 g + (size_t)(rb + row) * K + k0 + ch8 * 8);
        }
    };

    uint32_t offA[2], offB[4];
#pragma unroll
    for (int mt = 0; mt < 2; mt++)
        offA[mt] = (uint32_t)((wm + mt * 16 + (lane & 15)) * 144 + (lane >> 4) * 16);
#pragma unroll
    for (int nb = 0; nb < 4; nb++)
        offB[nb] = (uint32_t)((wn + nb * 16 + (lane & 15)) * 144 + (lane >> 4) * 16);

    load_stage(0, 0); cp_commit();
    load_stage(1, 1); cp_commit();

    for (int it = 0; it < NCH; ++it) {
        if (it + 1 < NCH) cp_wait<1>(); else cp_wait<0>();
        __syncthreads();
        if (it + 2 < NCH) { load_stage(it + 2, (it + 2) % 3); cp_commit(); }

        const uint32_t bA = sbase + (it % 3) * G1STAGE;
        const uint32_t bB = bA + TILE144;

#pragma unroll
        for (int kk = 0; kk < 4; kk++) {
            const uint32_t ks = kk * 32;
            uint32_t a[2][4], bfr[4][4];
#pragma unroll
            for (int mt = 0; mt < 2; mt++)
                ldsm4(a[mt][0], a[mt][1], a[mt][2], a[mt][3], bA + offA[mt] + ks);
#pragma unroll
            for (int nb = 0; nb < 4; nb++)
                ldsm4(bfr[nb][0], bfr[nb][1], bfr[nb][2], bfr[nb][3], bB + offB[nb] + ks);
#pragma unroll
            for (int mt = 0; mt < 2; mt++)
#pragma unroll
                for (int nb = 0; nb < 4; nb++)
#pragma unroll
                    for (int hf = 0; hf < 2; hf++)
                        mma16816f(acc[mt][nb * 2 + hf], a[mt],
                                  bfr[nb][hf], bfr[nb][hf + 2]);
        }
    }

    epilogue16<EPI>(acc, Ch, Cl, cosb, sinb, bm, bn, wm, wn, lane, N);
}

// ---------------- 1-pass fp16 -> fp32 out: O projection ----------------
__global__ __launch_bounds__(256) void gemm1p(
    const __half* __restrict__ A, const __half* __restrict__ B,
    float* __restrict__ C, int N, int K)
{
    extern __shared__ char smraw[];
    const uint32_t sbase = s2u32(smraw);
    const int tid  = threadIdx.x;
    const int wid  = tid >> 5;
    const int lane = tid & 31;
    const int bm = blockIdx.y << 7, bn = blockIdx.x << 7;
    const int wm = (wid & 3) * 32;
    const int wn = (wid >> 2) * 64;
    const int NCH = K >> 6;

    float acc[2][8][4];
#pragma unroll
    for (int i = 0; i < 2; i++)
#pragma unroll
        for (int j = 0; j < 8; j++)
#pragma unroll
            for (int t = 0; t < 4; t++) acc[i][j][t] = 0.0f;

    auto load_stage = [&](int ch, int st) {
        const int k0 = ch << 6;
        const uint32_t stb = sbase + st * G1STAGE;
#pragma unroll
        for (int i = 0; i < 8; i++) {
            int f = i * 256 + tid;
            int tile = f >> 10;
            int c = f & 1023;
            int row = c >> 3, ch8 = c & 7;
            const __half* g = tile ? B : A;
            int rb = tile ? bn : bm;
            cp16(stb + tile * TILE144 + row * 144 + ch8 * 16,
                 g + (size_t)(rb + row) * K + k0 + ch8 * 8);
        }
    };

    uint32_t offA[2], offB[4];
#pragma unroll
    for (int mt = 0; mt < 2; mt++)
        offA[mt] = (uint32_t)((wm + mt * 16 + (lane & 15)) * 144 + (lane >> 4) * 16);
#pragma unroll
    for (int nb = 0; nb < 4; nb++)
        offB[nb] = (uint32_t)((wn + nb * 16 + (lane & 15)) * 144 + (lane >> 4) * 16);

    load_stage(0, 0); cp_commit();
    load_stage(1, 1); cp_commit();

    for (int it = 0; it < NCH; ++it) {
        if (it + 1 < NCH) cp_wait<1>(); else cp_wait<0>();
        __syncthreads();
        if (it + 2 < NCH) { load_stage(it + 2, (it + 2) % 3); cp_commit(); }

        const uint32_t bA = sbase + (it % 3) * G1STAGE;
        const uint32_t bB = bA + TILE144;

#pragma unroll
        for (int kk = 0; kk < 4; kk++) {
            const uint32_t ks = kk * 32;
            uint32_t a[2][4], bfr[4][4];
#pragma unroll
            for (int mt = 0; mt < 2; mt++)
                ldsm4(a[mt][0], a[mt][1], a[mt][2], a[mt][3], bA + offA[mt] + ks);
#pragma unroll
            for (int nb = 0; nb < 4; nb++)
                ldsm4(bfr[nb][0], bfr[nb][1], bfr[nb][2], bfr[nb][3], bB + offB[nb] + ks);
#pragma unroll
            for (int mt = 0; mt < 2; mt++)
#pragma unroll
                for (int nb = 0; nb < 4; nb++)
#pragma unroll
                    for (int hf = 0; hf < 2; hf++)
                        mma16816f(acc[mt][nb * 2 + hf], a[mt],
                                  bfr[nb][hf], bfr[nb][hf + 2]);
        }
    }

#pragma unroll
    for (int mt = 0; mt < 2; mt++) {
        int r0 = bm + wm + mt * 16 + (lane >> 2);
#pragma unroll
        for (int nt = 0; nt < 8; nt++) {
            int c0 = bn + wn + nt * 8 + (lane & 3) * 2;
            float* p = acc[mt][nt];
            *(float2*)&C[(size_t)r0 * N + c0]       = make_float2(p[0], p[1]);
            *(float2*)&C[(size_t)(r0 + 8) * N + c0] = make_float2(p[2], p[3]);
        }
    }
}

// ---------------- flash attention via mma.sync ----------------
// 128 q-rows/CTA, 8 warps x 16 rows, 64-key tiles double buffered.
// S: Q hi/lo 2-pass vs K fp16; PV: fp16 single pass. fp32 softmax/accum.
// Grid reversed so longest (most-keys) tiles launch first.
#define APITCH  272
#define QS_BYTES (128 * APITCH)
#define KVTILE   (64 * APITCH)
#define STG      (2 * KVTILE)
#define ASMEM    (2 * QS_BYTES + 2 * STG)
__global__ __launch_bounds__(256) void attn_mma(
    const __half* __restrict__ Qh, const __half* __restrict__ Ql,
    const __half* __restrict__ Kk, const __half* __restrict__ V,
    __half* __restrict__ O16)
{
    extern __shared__ char smraw[];
    const uint32_t sb = s2u32(smraw);
    const uint32_t qh_s = sb;
    const uint32_t ql_s = sb + QS_BYTES;
    const uint32_t kvb  = sb + 2 * QS_BYTES;

    const int tid = threadIdx.x;
    const int wid = tid >> 5, lane = tid & 31;
    const int qt = gridDim.x - 1 - blockIdx.x;   // big tiles first
    const int bh = blockIdx.y;
    const int b = bh >> 5, h = bh & 31;
    const int kvh = h >> 2;

    {
        const size_t qrow0 = (size_t)(b * NSEQ + qt * 128) * DIMM + h * HDIM;
#pragma unroll
        for (int i = 0; i < 16; i++) {
            int f = i * 256 + tid;
            int tile = f >> 11;
            int c = f & 2047;
            int row = c >> 4, ch = c & 15;
            const __half* src = (tile ? Ql : Qh) + qrow0 + (size_t)row * DIMM + ch * 8;
            cp16((tile ? ql_s : qh_s) + row * APITCH + ch * 16, src);
        }
    }

    auto load_kv = [&](int kt, int st) {
        const uint32_t stb = kvb + st * STG;
        const size_t row0 = (size_t)(b * NSEQ + kt * 64) * KVDIM + kvh * HDIM;
#pragma unroll
        for (int i = 0; i < 8; i++) {
            int f = i * 256 + tid;
            int tile = f >> 10;
            int c = f & 1023;
            int row = c >> 4, ch = c & 15;
            const __half* src = (tile ? V : Kk) + row0 + (size_t)row * KVDIM + ch * 8;
            cp16(stb + tile * KVTILE + row * APITCH + ch * 16, src);
        }
    };

    float o[16][4];
#pragma unroll
    for (int t = 0; t < 16; t++)
#pragma unroll
        for (int r = 0; r < 4; r++) o[t][r] = 0.0f;
    float m0 = -1e30f, m1 = -1e30f, l0 = 0.0f, l1 = 0.0f;

    const int NIT = 2 * qt + 2;
    load_kv(0, 0); cp_commit();

    const int rowA = qt * 128 + wid * 16 + (lane >> 2);
    const uint32_t aoff = (uint32_t)((wid * 16 + (lane & 15)) * APITCH + (lane >> 4) * 16);

    for (int it = 0; it < NIT; it++) {
        const int st = it & 1;
        cp_wait<0>();
        __syncthreads();
        if (it + 1 < NIT) { load_kv(it + 1, st ^ 1); cp_commit(); }

        const uint32_t k_t = kvb + st * STG;
        const uint32_t v_t = k_t + KVTILE;

        float s[8][4];
#pragma unroll
        for (int t = 0; t < 8; t++)
#pragma unroll
            for (int r = 0; r < 4; r++) s[t][r] = 0.0f;

#pragma unroll
        for (int kki = 0; kki < 8; kki++) {
            uint32_t ah[4], al[4];
            ldsm4(ah[0], ah[1], ah[2], ah[3], qh_s + aoff + kki * 32);
            ldsm4(al[0], al[1], al[2], al[3], ql_s + aoff + kki * 32);
#pragma unroll
            for (int g = 0; g < 4; g++) {
                uint32_t boff = (uint32_t)((16 * g + (lane & 15)) * APITCH
                                           + (kki * 2 + (lane >> 4)) * 16);
                uint32_t b0, b1, b2, b3;
                ldsm4(b0, b1, b2, b3, k_t + boff);
                mma16816f(s[2 * g],     ah, b0, b2);
                mma16816f(s[2 * g],     al, b0, b2);
                mma16816f(s[2 * g + 1], ah, b1, b3);
                mma16816f(s[2 * g + 1], al, b1, b3);
            }
        }

        if (it >= 2 * qt) {
            const int kbase = it * 64 + (lane & 3) * 2;
#pragma unroll
            for (int t = 0; t < 8; t++) {
                int k0 = kbase + t * 8;
                if (k0     > rowA)     s[t][0] = -1e30f;
                if (k0 + 1 > rowA)     s[t][1] = -1e30f;
                if (k0     > rowA + 8) s[t][2] = -1e30f;
                if (k0 + 1 > rowA + 8) s[t][3] = -1e30f;
            }
        }

        float mxA = m0, mxB = m1;
#pragma unroll
        for (int t = 0; t < 8; t++) {
            mxA = fmaxf(mxA, fmaxf(s[t][0], s[t][1]));
            mxB = fmaxf(mxB, fmaxf(s[t][2], s[t][3]));
        }
        mxA = fmaxf(mxA, __shfl_xor_sync(0xFFFFFFFFu, mxA, 1));
        mxA = fmaxf(mxA, __shfl_xor_sync(0xFFFFFFFFu, mxA, 2));
        mxB = fmaxf(mxB, __shfl_xor_sync(0xFFFFFFFFu, mxB, 1));
        mxB = fmaxf(mxB, __shfl_xor_sync(0xFFFFFFFFu, mxB, 2));

        float aA = __expf(m0 - mxA), aB = __expf(m1 - mxB);
        float sA = 0.0f, sB = 0.0f;
#pragma unroll
        for (int t = 0; t < 8; t++) {
            s[t][0] = __expf(s[t][0] - mxA);
            s[t][1] = __expf(s[t][1] - mxA);
            s[t][2] = __expf(s[t][2] - mxB);
            s[t][3] = __expf(s[t][3] - mxB);
            sA += s[t][0] + s[t][1];
            sB += s[t][2] + s[t][3];
        }
        sA += __shfl_xor_sync(0xFFFFFFFFu, sA, 1);
        sA += __shfl_xor_sync(0xFFFFFFFFu, sA, 2);
        sB += __shfl_xor_sync(0xFFFFFFFFu, sB, 1);
        sB += __shfl_xor_sync(0xFFFFFFFFu, sB, 2);
        l0 = l0 * aA + sA;  l1 = l1 * aB + sB;
        m0 = mxA;           m1 = mxB;

#pragma unroll
        for (int t = 0; t < 16; t++) {
            o[t][0] *= aA; o[t][1] *= aA;
            o[t][2] *= aB; o[t][3] *= aB;
        }

        uint32_t ap[4][4];
#pragma unroll
        for (int kk = 0; kk < 4; kk++) {
            ap[kk][0] = packh2(s[2 * kk][0],     s[2 * kk][1]);
            ap[kk][1] = packh2(s[2 * kk][2],     s[2 * kk][3]);
            ap[kk][2] = packh2(s[2 * kk + 1][0], s[2 * kk + 1][1]);
            ap[kk][3] = packh2(s[2 * kk + 1][2], s[2 * kk + 1][3]);
        }
        const uint32_t vrow = (uint32_t)((((lane >> 3) & 1) * 8 + (lane & 7)) * APITCH
                                         + (lane >> 4) * 16);
#pragma unroll
        for (int kk = 0; kk < 4; kk++) {
#pragma unroll
            for (int g = 0; g < 8; g++) {
                uint32_t v0, v1, v2, v3;
                ldsm4t(v0, v1, v2, v3, v_t + vrow + (uint32_t)(16 * kk * APITCH + g * 32));
                mma16816f(o[2 * g],     ap[kk], v0, v1);
                mma16816f(o[2 * g + 1], ap[kk], v2, v3);
            }
        }
    }

    const float iA = 1.0f / l0, iB = 1.0f / l1;
    __half* obase = O16 + ((size_t)(b * NSEQ) * NHEAD + h) * HDIM;
#pragma unroll
    for (int t = 0; t < 16; t++) {
        int d = t * 8 + (lane & 3) * 2;
        *(__half2*)(obase + (size_t)rowA * (NHEAD * HDIM) + d) =
            __floats2half2_rn(o[t][0] * iA, o[t][1] * iA);
        *(__half2*)(obase + (size_t)(rowA + 8) * (NHEAD * HDIM) + d) =
            __floats2half2_rn(o[t][2] * iB, o[t][3] * iB);
    }
}

// ---------------- launch ----------------
extern "C" void kernel_launch(void* const* d_in, const int* in_sizes, int n_in,
                              void* d_out, int out_size)
{
    const float* x    = (const float*)d_in[0];
    const float* wq   = (const float*)d_in[1];
    const float* wk   = (const float*)d_in[2];
    const float* wv   = (const float*)d_in[3];
    const float* wo   = (const float*)d_in[4];
    const float* cosb = (const float*)d_in[5];
    const float* sinb = (const float*)d_in[6];
    float* out = (float*)d_out;

    __half *x16, *wq16, *wk16, *wv16, *wo16;
    cudaGetSymbolAddress((void**)&x16,  g_x16);
    cudaGetSymbolAddress((void**)&wq16, g_wq16);
    cudaGetSymbolAddress((void**)&wk16, g_wk16);
    cudaGetSymbolAddress((void**)&wv16, g_wv16);
    cudaGetSymbolAddress((void**)&wo16, g_wo16);
    __half *q16h, *q16l, *k16, *v16, *o16;
    cudaGetSymbolAddress((void**)&q16h, g_q16h);
    cudaGetSymbolAddress((void**)&q16l, g_q16l);
    cudaGetSymbolAddress((void**)&k16,  g_k16);
    cudaGetSymbolAddress((void**)&v16,  g_v16);
    cudaGetSymbolAddress((void**)&o16,  g_o16);

    cudaFuncSetAttribute(gemm1pe<0>, cudaFuncAttributeMaxDynamicSharedMemorySize, G1SMEM);
    cudaFuncSetAttribute(gemm1pe<1>, cudaFuncAttributeMaxDynamicSharedMemorySize, G1SMEM);
    cudaFuncSetAttribute(gemm1pe<2>, cudaFuncAttributeMaxDynamicSharedMemorySize, G1SMEM);
    cudaFuncSetAttribute(gemm1p, cudaFuncAttributeMaxDynamicSharedMemorySize, G1SMEM);
    cudaFuncSetAttribute(attn_mma, cudaFuncAttributeMaxDynamicSharedMemorySize, ASMEM);

    dim3 blk(256);

    // all fp32 -> fp16 conversions in one launch
    cvt_all_kernel<<<(C_TOT + 255) / 256, blk>>>(
        x, wq, wk, wv, wo, x16, wq16, wk16, wv16, wo16);

    // projections: all 1-pass fp16 with fused epilogues
    gemm1pe<0><<<dim3(DIMM / 128, MROWS / 128), blk, G1SMEM>>>(
        x16, wq16, q16h, q16l, cosb, sinb, DIMM, DIMM);       // Q: rope+scale+hi/lo
    gemm1pe<1><<<dim3(KVDIM / 128, MROWS / 128), blk, G1SMEM>>>(
        x16, wk16, k16, nullptr, cosb, sinb, KVDIM, DIMM);    // K: rope
    gemm1pe<2><<<dim3(KVDIM / 128, MROWS / 128), blk, G1SMEM>>>(
        x16, wv16, v16, nullptr, cosb, sinb, KVDIM, DIMM);    // V

    // attention (Q hi/lo, K/V fp16) -> fp16 o16
    attn_mma<<<dim3(NSEQ / 128, BATCH * NHEAD), blk, ASMEM>>>(q16h, q16l, k16, v16, o16);

    // output projection: single-pass fp16, fp32 out
    gemm1p<<<dim3(DIMM / 128, MROWS / 128), blk, G1SMEM>>>(o16, wo16, out, DIMM, DIMM);
}

// round 16
// speedup vs baseline: 1.2257x; 1.1150x over previous
#include <cuda_runtime.h>
#include <cuda_fp16.h>
#include <cstdint>

// ---------------- constants ----------------
#define BATCH   2
#define NSEQ    2048
#define DIMM    4096
#define NHEAD   32
#define NKV     8
#define HDIM    128
#define MROWS   (BATCH*NSEQ)            // 4096
#define KVDIM   (NKV*HDIM)              // 1024
#define NQKV    (DIMM + 2 * KVDIM)      // 6144
#define ATT_SCALE 0.08838834764831845f  // 1/sqrt(128)

// ---------------- scratch (device globals; no allocations allowed) ----------------
__device__ __half g_x16[MROWS * DIMM];
__device__ __half g_wqkv16[NQKV * DIMM];   // [wq; wk; wv] fused, row-major [6144, 4096]
__device__ __half g_wo16[DIMM * DIMM];

__device__ __half g_q16h[MROWS * DIMM], g_q16l[MROWS * DIMM];  // roped+scaled Q hi/lo
__device__ __half g_k16[MROWS * KVDIM];                        // roped K
__device__ __half g_v16[MROWS * KVDIM];
__device__ __half g_o16[MROWS * DIMM];

// ---------------- PTX helpers (plain sm_80+ PTX) ----------------
__device__ __forceinline__ uint32_t s2u32(const void* p) {
    uint32_t a;
    asm("{ .reg .u64 t; cvta.to.shared.u64 t, %1; cvt.u32.u64 %0, t; }" : "=r"(a) : "l"(p));
    return a;
}
__device__ __forceinline__ void cp16(uint32_t d, const void* s) {
    asm volatile("cp.async.cg.shared.global [%0], [%1], 16;" :: "r"(d), "l"(s));
}
__device__ __forceinline__ void cp_commit() {
    asm volatile("cp.async.commit_group;" ::: "memory");
}
template <int N>
__device__ __forceinline__ void cp_wait() {
    asm volatile("cp.async.wait_group %0;" :: "n"(N) : "memory");
}
__device__ __forceinline__ void ldsm4(uint32_t& r0, uint32_t& r1, uint32_t& r2,
                                      uint32_t& r3, uint32_t addr) {
    asm volatile("ldmatrix.sync.aligned.m8n8.x4.shared.b16 {%0,%1,%2,%3}, [%4];"
                 : "=r"(r0), "=r"(r1), "=r"(r2), "=r"(r3) : "r"(addr));
}
__device__ __forceinline__ void ldsm4t(uint32_t& r0, uint32_t& r1, uint32_t& r2,
                                       uint32_t& r3, uint32_t addr) {
    asm volatile("ldmatrix.sync.aligned.m8n8.x4.trans.shared.b16 {%0,%1,%2,%3}, [%4];"
                 : "=r"(r0), "=r"(r1), "=r"(r2), "=r"(r3) : "r"(addr));
}
__device__ __forceinline__ void mma16816f(float* c, const uint32_t* a, uint32_t b0, uint32_t b1) {
    asm volatile(
        "mma.sync.aligned.m16n8k16.row.col.f32.f16.f16.f32 "
        "{%0,%1,%2,%3}, {%4,%5,%6,%7}, {%8,%9}, {%0,%1,%2,%3};"
        : "+f"(c[0]), "+f"(c[1]), "+f"(c[2]), "+f"(c[3])
        : "r"(a[0]), "r"(a[1]), "r"(a[2]), "r"(a[3]), "r"(b0), "r"(b1));
}
__device__ __forceinline__ uint32_t packh2(float x, float y) {
    __half2 h = __floats2half2_rn(x, y);
    return *(uint32_t*)&h;
}

// ---------------- fused fp32 -> fp16 conversion (x, wq|wk|wv fused, wo) ----------------
#define C_X   (MROWS * DIMM / 4)
#define C_WQ  (DIMM * DIMM / 4)
#define C_WK  (KVDIM * DIMM / 4)
#define C_WV  (KVDIM * DIMM / 4)
#define C_WO  (DIMM * DIMM / 4)
#define C_TOT (C_X + C_WQ + C_WK + C_WV + C_WO)
__global__ __launch_bounds__(256) void cvt_all_kernel(
    const float* __restrict__ x,  const float* __restrict__ wq,
    const float* __restrict__ wk, const float* __restrict__ wv,
    const float* __restrict__ wo,
    __half* __restrict__ x16, __half* __restrict__ wqkv16, __half* __restrict__ wo16)
{
    int i = blockIdx.x * blockDim.x + threadIdx.x;
    if (i >= C_TOT) return;
    const float* s; __half* d; int off;
    if (i < C_X) {
        s = x; d = x16; off = i;
    } else if (i < C_X + C_WQ) {
        s = wq; d = wqkv16; off = i - C_X;
    } else if (i < C_X + C_WQ + C_WK) {
        s = wk; d = wqkv16 + (size_t)DIMM * DIMM / 4 * 0 + (size_t)DIMM * DIMM;  // rows 4096..5119
        off = i - C_X - C_WQ;
    } else if (i < C_X + C_WQ + C_WK + C_WV) {
        s = wv; d = wqkv16 + (size_t)(DIMM + KVDIM) * DIMM;                      // rows 5120..6143
        off = i - C_X - C_WQ - C_WK;
    } else {
        s = wo; d = wo16; off = i - C_X - C_WQ - C_WK - C_WV;
    }
    float4 v = ((const float4*)s)[off];
    ((__half2*)d)[2 * off]     = __floats2half2_rn(v.x, v.y);
    ((__half2*)d)[2 * off + 1] = __floats2half2_rn(v.z, v.w);
}

// =====================================================================
// GEMM: C[M,N] = A[M,K] * B[N,K]^T, fp16 in, fp32 accum.
// CTA 128x128, BK=64, 256 thr (8 warps, warp tile 32x64), 3-stage cp.async,
// single __syncthreads per iteration, pitch 144B (conflict-free ldmatrix).
// =====================================================================
#define TILE144 (128 * 144)

// fused epilogues:
//  EPI 0: rope + ATT_SCALE + hi/lo fp16 split -> Ch, Cl   (Q)
//  EPI 1: rope + fp16 -> Ch                                (K)
//  EPI 2: fp16 -> Ch                                       (V)
template <int EPI>
__device__ __forceinline__ void epilogue16(
    float acc[2][8][4], __half* Ch, __half* Cl,
    const float* cosb, const float* sinb,
    int bm, int bn, int wm, int wn, int lane, int N)
{
#pragma unroll
    for (int mt = 0; mt < 2; mt++) {
        int r0 = bm + wm + mt * 16 + (lane >> 2);
        int n0 = r0 & (NSEQ - 1);
#pragma unroll
        for (int nt = 0; nt < 8; nt++) {
            int c0 = bn + wn + nt * 8 + (lane & 3) * 2;
            float* p = acc[mt][nt];
            float p0 = p[0], p1 = p[1], p2 = p[2], p3 = p[3];
            if (EPI <= 1) {
                int j = (c0 & (HDIM - 1)) >> 1;
                float ca = cosb[n0 * 64 + j],       sa = sinb[n0 * 64 + j];
                float cb = cosb[(n0 + 8) * 64 + j], sb = sinb[(n0 + 8) * 64 + j];
                float t0 = p0 * ca - p1 * sa, t1 = p0 * sa + p1 * ca;
                float t2 = p2 * cb - p3 * sb, t3 = p2 * sb + p3 * cb;
                p0 = t0; p1 = t1; p2 = t2; p3 = t3;
            }
            if (EPI == 0) {
                p0 *= ATT_SCALE; p1 *= ATT_SCALE; p2 *= ATT_SCALE; p3 *= ATT_SCALE;
                __half h0 = __float2half_rn(p0), h1 = __float2half_rn(p1);
                __half h2 = __float2half_rn(p2), h3 = __float2half_rn(p3);
                *(__half2*)&Ch[(size_t)r0 * N + c0]       = __halves2half2(h0, h1);
                *(__half2*)&Ch[(size_t)(r0 + 8) * N + c0] = __halves2half2(h2, h3);
                *(__half2*)&Cl[(size_t)r0 * N + c0] = __halves2half2(
                    __float2half_rn(p0 - __half2float(h0)),
                    __float2half_rn(p1 - __half2float(h1)));
                *(__half2*)&Cl[(size_t)(r0 + 8) * N + c0] = __halves2half2(
                    __float2half_rn(p2 - __half2float(h2)),
                    __float2half_rn(p3 - __half2float(h3)));
            } else {
                *(__half2*)&Ch[(size_t)r0 * N + c0]       = __floats2half2_rn(p0, p1);
                *(__half2*)&Ch[(size_t)(r0 + 8) * N + c0] = __floats2half2_rn(p2, p3);
            }
        }
    }
}

// ---------------- fused QKV projection: one GEMM, per-CTA epilogue dispatch ----------------
// B = [wq; wk; wv] (N = 6144). bn < 4096 -> Q; bn < 5120 -> K; else V.
#define G1STAGE (2 * TILE144)        // 36864
#define G1SMEM  (3 * G1STAGE)        // 110592
__global__ __launch_bounds__(256, 2) void gemm_qkv(
    const __half* __restrict__ A, const __half* __restrict__ B,
    __half* __restrict__ Qh, __half* __restrict__ Ql,
    __half* __restrict__ Kd, __half* __restrict__ Vd,
    const float* __restrict__ cosb, const float* __restrict__ sinb, int K)
{
    extern __shared__ char smraw[];
    const uint32_t sbase = s2u32(smraw);
    const int tid  = threadIdx.x;
    const int wid  = tid >> 5;
    const int lane = tid & 31;
    const int bm = blockIdx.y << 7, bn = blockIdx.x << 7;
    const int wm = (wid & 3) * 32;
    const int wn = (wid >> 2) * 64;
    const int NCH = K >> 6;

    float acc[2][8][4];
#pragma unroll
    for (int i = 0; i < 2; i++)
#pragma unroll
        for (int j = 0; j < 8; j++)
#pragma unroll
            for (int t = 0; t < 4; t++) acc[i][j][t] = 0.0f;

    auto load_stage = [&](int ch, int st) {
        const int k0 = ch << 6;
        const uint32_t stb = sbase + st * G1STAGE;
#pragma unroll
        for (int i = 0; i < 8; i++) {
            int f = i * 256 + tid;
            int tile = f >> 10;
            int c = f & 1023;
            int row = c >> 3, ch8 = c & 7;
            const __half* g = tile ? B : A;
            int rb = tile ? bn : bm;
            cp16(stb + tile * TILE144 + row * 144 + ch8 * 16,
                 g + (size_t)(rb + row) * K + k0 + ch8 * 8);
        }
    };

    uint32_t offA[2], offB[4];
#pragma unroll
    for (int mt = 0; mt < 2; mt++)
        offA[mt] = (uint32_t)((wm + mt * 16 + (lane & 15)) * 144 + (lane >> 4) * 16);
#pragma unroll
    for (int nb = 0; nb < 4; nb++)
        offB[nb] = (uint32_t)((wn + nb * 16 + (lane & 15)) * 144 + (lane >> 4) * 16);

    load_stage(0, 0); cp_commit();
    load_stage(1, 1); cp_commit();

    for (int it = 0; it < NCH; ++it) {
        if (it + 1 < NCH) cp_wait<1>(); else cp_wait<0>();
        __syncthreads();
        if (it + 2 < NCH) { load_stage(it + 2, (it + 2) % 3); cp_commit(); }

        const uint32_t bA = sbase + (it % 3) * G1STAGE;
        const uint32_t bB = bA + TILE144;

#pragma unroll
        for (int kk = 0; kk < 4; kk++) {
            const uint32_t ks = kk * 32;
            uint32_t a[2][4], bfr[4][4];
#pragma unroll
            for (int mt = 0; mt < 2; mt++)
                ldsm4(a[mt][0], a[mt][1], a[mt][2], a[mt][3], bA + offA[mt] + ks);
#pragma unroll
            for (int nb = 0; nb < 4; nb++)
                ldsm4(bfr[nb][0], bfr[nb][1], bfr[nb][2], bfr[nb][3], bB + offB[nb] + ks);
#pragma unroll
            for (int mt = 0; mt < 2; mt++)
#pragma unroll
                for (int nb = 0; nb < 4; nb++)
#pragma unroll
                    for (int hf = 0; hf < 2; hf++)
                        mma16816f(acc[mt][nb * 2 + hf], a[mt],
                                  bfr[nb][hf], bfr[nb][hf + 2]);
        }
    }

    // per-CTA epilogue dispatch (bn boundaries are CTA-tile aligned)
    if (bn < DIMM) {
        epilogue16<0>(acc, Qh, Ql, cosb, sinb, bm, bn, wm, wn, lane, DIMM);
    } else if (bn < DIMM + KVDIM) {
        epilogue16<1>(acc, Kd, nullptr, cosb, sinb, bm, bn - DIMM, wm, wn, lane, KVDIM);
    } else {
        epilogue16<2>(acc, Vd, nullptr, cosb, sinb, bm, bn - DIMM - KVDIM, wm, wn, lane, KVDIM);
    }
}

// ---------------- 1-pass fp16 -> fp32 out: O projection ----------------
__global__ __launch_bounds__(256, 2) void gemm1p(
    const __half* __restrict__ A, const __half* __restrict__ B,
    float* __restrict__ C, int N, int K)
{
    extern __shared__ char smraw[];
    const uint32_t sbase = s2u32(smraw);
    const int tid  = threadIdx.x;
    const int wid  = tid >> 5;
    const int lane = tid & 31;
    const int bm = blockIdx.y << 7, bn = blockIdx.x << 7;
    const int wm = (wid & 3) * 32;
    const int wn = (wid >> 2) * 64;
    const int NCH = K >> 6;

    float acc[2][8][4];
#pragma unroll
    for (int i = 0; i < 2; i++)
#pragma unroll
        for (int j = 0; j < 8; j++)
#pragma unroll
            for (int t = 0; t < 4; t++) acc[i][j][t] = 0.0f;

    auto load_stage = [&](int ch, int st) {
        const int k0 = ch << 6;
        const uint32_t stb = sbase + st * G1STAGE;
#pragma unroll
        for (int i = 0; i < 8; i++) {
            int f = i * 256 + tid;
            int tile = f >> 10;
            int c = f & 1023;
            int row = c >> 3, ch8 = c & 7;
            const __half* g = tile ? B : A;
            int rb = tile ? bn : bm;
            cp16(stb + tile * TILE144 + row * 144 + ch8 * 16,
                 g + (size_t)(rb + row) * K + k0 + ch8 * 8);
        }
    };

    uint32_t offA[2], offB[4];
#pragma unroll
    for (int mt = 0; mt < 2; mt++)
        offA[mt] = (uint32_t)((wm + mt * 16 + (lane & 15)) * 144 + (lane >> 4) * 16);
#pragma unroll
    for (int nb = 0; nb < 4; nb++)
        offB[nb] = (uint32_t)((wn + nb * 16 + (lane & 15)) * 144 + (lane >> 4) * 16);

    load_stage(0, 0); cp_commit();
    load_stage(1, 1); cp_commit();

    for (int it = 0; it < NCH; ++it) {
        if (it + 1 < NCH) cp_wait<1>(); else cp_wait<0>();
        __syncthreads();
        if (it + 2 < NCH) { load_stage(it + 2, (it + 2) % 3); cp_commit(); }

        const uint32_t bA = sbase + (it % 3) * G1STAGE;
        const uint32_t bB = bA + TILE144;

#pragma unroll
        for (int kk = 0; kk < 4; kk++) {
            const uint32_t ks = kk * 32;
            uint32_t a[2][4], bfr[4][4];
#pragma unroll
            for (int mt = 0; mt < 2; mt++)
                ldsm4(a[mt][0], a[mt][1], a[mt][2], a[mt][3], bA + offA[mt] + ks);
#pragma unroll
            for (int nb = 0; nb < 4; nb++)
                ldsm4(bfr[nb][0], bfr[nb][1], bfr[nb][2], bfr[nb][3], bB + offB[nb] + ks);
#pragma unroll
            for (int mt = 0; mt < 2; mt++)
#pragma unroll
                for (int nb = 0; nb < 4; nb++)
#pragma unroll
                    for (int hf = 0; hf < 2; hf++)
                        mma16816f(acc[mt][nb * 2 + hf], a[mt],
                                  bfr[nb][hf], bfr[nb][hf + 2]);
        }
    }

#pragma unroll
    for (int mt = 0; mt < 2; mt++) {
        int r0 = bm + wm + mt * 16 + (lane >> 2);
#pragma unroll
        for (int nt = 0; nt < 8; nt++) {
            int c0 = bn + wn + nt * 8 + (lane & 3) * 2;
            float* p = acc[mt][nt];
            *(float2*)&C[(size_t)r0 * N + c0]       = make_float2(p[0], p[1]);
            *(float2*)&C[(size_t)(r0 + 8) * N + c0] = make_float2(p[2], p[3]);
        }
    }
}

// ---------------- flash attention via mma.sync (unchanged) ----------------
#define APITCH  272
#define QS_BYTES (128 * APITCH)
#define KVTILE   (64 * APITCH)
#define STG      (2 * KVTILE)
#define ASMEM    (2 * QS_BYTES + 2 * STG)
__global__ __launch_bounds__(256) void attn_mma(
    const __half* __restrict__ Qh, const __half* __restrict__ Ql,
    const __half* __restrict__ Kk, const __half* __restrict__ V,
    __half* __restrict__ O16)
{
    extern __shared__ char smraw[];
    const uint32_t sb = s2u32(smraw);
    const uint32_t qh_s = sb;
    const uint32_t ql_s = sb + QS_BYTES;
    const uint32_t kvb  = sb + 2 * QS_BYTES;

    const int tid = threadIdx.x;
    const int wid = tid >> 5, lane = tid & 31;
    const int qt = gridDim.x - 1 - blockIdx.x;
    const int bh = blockIdx.y;
    const int b = bh >> 5, h = bh & 31;
    const int kvh = h >> 2;

    {
        const size_t qrow0 = (size_t)(b * NSEQ + qt * 128) * DIMM + h * HDIM;
#pragma unroll
        for (int i = 0; i < 16; i++) {
            int f = i * 256 + tid;
            int tile = f >> 11;
            int c = f & 2047;
            int row = c >> 4, ch = c & 15;
            const __half* src = (tile ? Ql : Qh) + qrow0 + (size_t)row * DIMM + ch * 8;
            cp16((tile ? ql_s : qh_s) + row * APITCH + ch * 16, src);
        }
    }

    auto load_kv = [&](int kt, int st) {
        const uint32_t stb = kvb + st * STG;
        const size_t row0 = (size_t)(b * NSEQ + kt * 64) * KVDIM + kvh * HDIM;
#pragma unroll
        for (int i = 0; i < 8; i++) {
            int f = i * 256 + tid;
            int tile = f >> 10;
            int c = f & 1023;
            int row = c >> 4, ch = c & 15;
            const __half* src = (tile ? V : Kk) + row0 + (size_t)row * KVDIM + ch * 8;
            cp16(stb + tile * KVTILE + row * APITCH + ch * 16, src);
        }
    };

    float o[16][4];
#pragma unroll
    for (int t = 0; t < 16; t++)
#pragma unroll
        for (int r = 0; r < 4; r++) o[t][r] = 0.0f;
    float m0 = -1e30f, m1 = -1e30f, l0 = 0.0f, l1 = 0.0f;

    const int NIT = 2 * qt + 2;
    load_kv(0, 0); cp_commit();

    const int rowA = qt * 128 + wid * 16 + (lane >> 2);
    const uint32_t aoff = (uint32_t)((wid * 16 + (lane & 15)) * APITCH + (lane >> 4) * 16);

    for (int it = 0; it < NIT; it++) {
        const int st = it & 1;
        cp_wait<0>();
        __syncthreads();
        if (it + 1 < NIT) { load_kv(it + 1, st ^ 1); cp_commit(); }

        const uint32_t k_t = kvb + st * STG;
        const uint32_t v_t = k_t + KVTILE;

        float s[8][4];
#pragma unroll
        for (int t = 0; t < 8; t++)
#pragma unroll
            for (int r = 0; r < 4; r++) s[t][r] = 0.0f;

#pragma unroll
        for (int kki = 0; kki < 8; kki++) {
            uint32_t ah[4], al[4];
            ldsm4(ah[0], ah[1], ah[2], ah[3], qh_s + aoff + kki * 32);
            ldsm4(al[0], al[1], al[2], al[3], ql_s + aoff + kki * 32);
#pragma unroll
            for (int g = 0; g < 4; g++) {
                uint32_t boff = (uint32_t)((16 * g + (lane & 15)) * APITCH
                                           + (kki * 2 + (lane >> 4)) * 16);
                uint32_t b0, b1, b2, b3;
                ldsm4(b0, b1, b2, b3, k_t + boff);
                mma16816f(s[2 * g],     ah, b0, b2);
                mma16816f(s[2 * g],     al, b0, b2);
                mma16816f(s[2 * g + 1], ah, b1, b3);
                mma16816f(s[2 * g + 1], al, b1, b3);
            }
        }

        if (it >= 2 * qt) {
            const int kbase = it * 64 + (lane & 3) * 2;
#pragma unroll
            for (int t = 0; t < 8; t++) {
                int k0 = kbase + t * 8;
                if (k0     > rowA)     s[t][0] = -1e30f;
                if (k0 + 1 > rowA)     s[t][1] = -1e30f;
                if (k0     > rowA + 8) s[t][2] = -1e30f;
                if (k0 + 1 > rowA + 8) s[t][3] = -1e30f;
            }
        }

        float mxA = m0, mxB = m1;
#pragma unroll
        for (int t = 0; t < 8; t++) {
            mxA = fmaxf(mxA, fmaxf(s[t][0], s[t][1]));
            mxB = fmaxf(mxB, fmaxf(s[t][2], s[t][3]));
        }
        mxA = fmaxf(mxA, __shfl_xor_sync(0xFFFFFFFFu, mxA, 1));
        mxA = fmaxf(mxA, __shfl_xor_sync(0xFFFFFFFFu, mxA, 2));
        mxB = fmaxf(mxB, __shfl_xor_sync(0xFFFFFFFFu, mxB, 1));
        mxB = fmaxf(mxB, __shfl_xor_sync(0xFFFFFFFFu, mxB, 2));

        float aA = __expf(m0 - mxA), aB = __expf(m1 - mxB);
        float sA = 0.0f, sB = 0.0f;
#pragma unroll
        for (int t = 0; t < 8; t++) {
            s[t][0] = __expf(s[t][0] - mxA);
            s[t][1] = __expf(s[t][1] - mxA);
            s[t][2] = __expf(s[t][2] - mxB);
            s[t][3] = __expf(s[t][3] - mxB);
            sA += s[t][0] + s[t][1];
            sB += s[t][2] + s[t][3];
        }
        sA += __shfl_xor_sync(0xFFFFFFFFu, sA, 1);
        sA += __shfl_xor_sync(0xFFFFFFFFu, sA, 2);
        sB += __shfl_xor_sync(0xFFFFFFFFu, sB, 1);
        sB += __shfl_xor_sync(0xFFFFFFFFu, sB, 2);
        l0 = l0 * aA + sA;  l1 = l1 * aB + sB;
        m0 = mxA;           m1 = mxB;

#pragma unroll
        for (int t = 0; t < 16; t++) {
            o[t][0] *= aA; o[t][1] *= aA;
            o[t][2] *= aB; o[t][3] *= aB;
        }

        uint32_t ap[4][4];
#pragma unroll
        for (int kk = 0; kk < 4; kk++) {
            ap[kk][0] = packh2(s[2 * kk][0],     s[2 * kk][1]);
            ap[kk][1] = packh2(s[2 * kk][2],     s[2 * kk][3]);
            ap[kk][2] = packh2(s[2 * kk + 1][0], s[2 * kk + 1][1]);
            ap[kk][3] = packh2(s[2 * kk + 1][2], s[2 * kk + 1][3]);
        }
        const uint32_t vrow = (uint32_t)((((lane >> 3) & 1) * 8 + (lane & 7)) * APITCH
                                         + (lane >> 4) * 16);
#pragma unroll
        for (int kk = 0; kk < 4; kk++) {
#pragma unroll
            for (int g = 0; g < 8; g++) {
                uint32_t v0, v1, v2, v3;
                ldsm4t(v0, v1, v2, v3, v_t + vrow + (uint32_t)(16 * kk * APITCH + g * 32));
                mma16816f(o[2 * g],     ap[kk], v0, v1);
                mma16816f(o[2 * g + 1], ap[kk], v2, v3);
            }
        }
    }

    const float iA = 1.0f / l0, iB = 1.0f / l1;
    __half* obase = O16 + ((size_t)(b * NSEQ) * NHEAD + h) * HDIM;
#pragma unroll
    for (int t = 0; t < 16; t++) {
        int d = t * 8 + (lane & 3) * 2;
        *(__half2*)(obase + (size_t)rowA * (NHEAD * HDIM) + d) =
            __floats2half2_rn(o[t][0] * iA, o[t][1] * iA);
        *(__half2*)(obase + (size_t)(rowA + 8) * (NHEAD * HDIM) + d) =
            __floats2half2_rn(o[t][2] * iB, o[t][3] * iB);
    }
}

// ---------------- launch ----------------
extern "C" void kernel_launch(void* const* d_in, const int* in_sizes, int n_in,
                              void* d_out, int out_size)
{
    const float* x    = (const float*)d_in[0];
    const float* wq   = (const float*)d_in[1];
    const float* wk   = (const float*)d_in[2];
    const float* wv   = (const float*)d_in[3];
    const float* wo   = (const float*)d_in[4];
    const float* cosb = (const float*)d_in[5];
    const float* sinb = (const float*)d_in[6];
    float* out = (float*)d_out;

    __half *x16, *wqkv16, *wo16;
    cudaGetSymbolAddress((void**)&x16,    g_x16);
    cudaGetSymbolAddress((void**)&wqkv16, g_wqkv16);
    cudaGetSymbolAddress((void**)&wo16,   g_wo16);
    __half *q16h, *q16l, *k16, *v16, *o16;
    cudaGetSymbolAddress((void**)&q16h, g_q16h);
    cudaGetSymbolAddress((void**)&q16l, g_q16l);
    cudaGetSymbolAddress((void**)&k16,  g_k16);
    cudaGetSymbolAddress((void**)&v16,  g_v16);
    cudaGetSymbolAddress((void**)&o16,  g_o16);

    cudaFuncSetAttribute(gemm_qkv, cudaFuncAttributeMaxDynamicSharedMemorySize, G1SMEM);
    cudaFuncSetAttribute(gemm1p,   cudaFuncAttributeMaxDynamicSharedMemorySize, G1SMEM);
    cudaFuncSetAttribute(attn_mma, cudaFuncAttributeMaxDynamicSharedMemorySize, ASMEM);

    dim3 blk(256);

    // all fp32 -> fp16 conversions in one launch (weights fused into wqkv16)
    cvt_all_kernel<<<(C_TOT + 255) / 256, blk>>>(x, wq, wk, wv, wo, x16, wqkv16, wo16);

    // fused QKV projection (rope/scale/split epilogues dispatched per CTA)
    gemm_qkv<<<dim3(NQKV / 128, MROWS / 128), blk, G1SMEM>>>(
        x16, wqkv16, q16h, q16l, k16, v16, cosb, sinb, DIMM);

    // attention (Q hi/lo, K/V fp16) -> fp16 o16
    attn_mma<<<dim3(NSEQ / 128, BATCH * NHEAD), blk, ASMEM>>>(q16h, q16l, k16, v16, o16);

    // output projection: single-pass fp16, fp32 out
    gemm1p<<<dim3(DIMM / 128, MROWS / 128), blk, G1SMEM>>>(o16, wo16, out, DIMM, DIMM);
}

// round 17
// speedup vs baseline: 1.2846x; 1.0480x over previous
#include <cuda_runtime.h>
#include <cuda_fp16.h>
#include <cstdint>

// ---------------- constants ----------------
#define BATCH   2
#define NSEQ    2048
#define DIMM    4096
#define NHEAD   32
#define NKV     8
#define HDIM    128
#define MROWS   (BATCH*NSEQ)            // 4096
#define KVDIM   (NKV*HDIM)              // 1024
#define NQKV    (DIMM + 2 * KVDIM)      // 6144
#define ATT_SCALE 0.08838834764831845f  // 1/sqrt(128)

// ---------------- scratch (device globals; no allocations allowed) ----------------
__device__ __half g_x16[MROWS * DIMM];
__device__ __half g_wqkv16[NQKV * DIMM];   // [wq; wk; wv] fused, row-major [6144, 4096]
__device__ __half g_wo16[DIMM * DIMM];

__device__ __half g_q16[MROWS * DIMM];     // roped+scaled Q (fp16, single)
__device__ __half g_k16[MROWS * KVDIM];    // roped K
__device__ __half g_v16[MROWS * KVDIM];
__device__ __half g_o16[MROWS * DIMM];

// ---------------- PTX helpers (plain sm_80+ PTX) ----------------
__device__ __forceinline__ uint32_t s2u32(const void* p) {
    uint32_t a;
    asm("{ .reg .u64 t; cvta.to.shared.u64 t, %1; cvt.u32.u64 %0, t; }" : "=r"(a) : "l"(p));
    return a;
}
__device__ __forceinline__ void cp16(uint32_t d, const void* s) {
    asm volatile("cp.async.cg.shared.global [%0], [%1], 16;" :: "r"(d), "l"(s));
}
__device__ __forceinline__ void cp_commit() {
    asm volatile("cp.async.commit_group;" ::: "memory");
}
template <int N>
__device__ __forceinline__ void cp_wait() {
    asm volatile("cp.async.wait_group %0;" :: "n"(N) : "memory");
}
__device__ __forceinline__ void ldsm4(uint32_t& r0, uint32_t& r1, uint32_t& r2,
                                      uint32_t& r3, uint32_t addr) {
    asm volatile("ldmatrix.sync.aligned.m8n8.x4.shared.b16 {%0,%1,%2,%3}, [%4];"
                 : "=r"(r0), "=r"(r1), "=r"(r2), "=r"(r3) : "r"(addr));
}
__device__ __forceinline__ void ldsm4t(uint32_t& r0, uint32_t& r1, uint32_t& r2,
                                       uint32_t& r3, uint32_t addr) {
    asm volatile("ldmatrix.sync.aligned.m8n8.x4.trans.shared.b16 {%0,%1,%2,%3}, [%4];"
                 : "=r"(r0), "=r"(r1), "=r"(r2), "=r"(r3) : "r"(addr));
}
__device__ __forceinline__ void mma16816f(float* c, const uint32_t* a, uint32_t b0, uint32_t b1) {
    asm volatile(
        "mma.sync.aligned.m16n8k16.row.col.f32.f16.f16.f32 "
        "{%0,%1,%2,%3}, {%4,%5,%6,%7}, {%8,%9}, {%0,%1,%2,%3};"
        : "+f"(c[0]), "+f"(c[1]), "+f"(c[2]), "+f"(c[3])
        : "r"(a[0]), "r"(a[1]), "r"(a[2]), "r"(a[3]), "r"(b0), "r"(b1));
}
__device__ __forceinline__ uint32_t packh2(float x, float y) {
    __half2 h = __floats2half2_rn(x, y);
    return *(uint32_t*)&h;
}

// ---------------- fused fp32 -> fp16 conversion, MLP=4 grid-stride ----------------
#define C_X   (MROWS * DIMM / 4)
#define C_WQ  (DIMM * DIMM / 4)
#define C_WK  (KVDIM * DIMM / 4)
#define C_WV  (KVDIM * DIMM / 4)
#define C_WO  (DIMM * DIMM / 4)
#define C_TOT (C_X + C_WQ + C_WK + C_WV + C_WO)
#define CVT_GRID ((C_TOT + 4 * 256 - 1) / (4 * 256))
__global__ __launch_bounds__(256) void cvt_all_kernel(
    const float* __restrict__ x,  const float* __restrict__ wq,
    const float* __restrict__ wk, const float* __restrict__ wv,
    const float* __restrict__ wo,
    __half* __restrict__ x16, __half* __restrict__ wqkv16, __half* __restrict__ wo16)
{
    const int stride = CVT_GRID * 256;
    const int base = blockIdx.x * 256 + threadIdx.x;

    const float* s[4]; __half* d[4]; int off[4]; bool act[4];
    float4 v[4];
#pragma unroll
    for (int j = 0; j < 4; j++) {
        int i = base + j * stride;
        act[j] = (i < C_TOT);
        if (!act[j]) { s[j] = x; d[j] = x16; off[j] = 0; continue; }
        if (i < C_X) {
            s[j] = x; d[j] = x16; off[j] = i;
        } else if (i < C_X + C_WQ) {
            s[j] = wq; d[j] = wqkv16; off[j] = i - C_X;
        } else if (i < C_X + C_WQ + C_WK) {
            s[j] = wk; d[j] = wqkv16 + (size_t)DIMM * DIMM; off[j] = i - C_X - C_WQ;
        } else if (i < C_X + C_WQ + C_WK + C_WV) {
            s[j] = wv; d[j] = wqkv16 + (size_t)(DIMM + KVDIM) * DIMM;
            off[j] = i - C_X - C_WQ - C_WK;
        } else {
            s[j] = wo; d[j] = wo16; off[j] = i - C_X - C_WQ - C_WK - C_WV;
        }
    }
#pragma unroll
    for (int j = 0; j < 4; j++)
        if (act[j]) v[j] = ((const float4*)s[j])[off[j]];
#pragma unroll
    for (int j = 0; j < 4; j++) {
        if (!act[j]) continue;
        ((__half2*)d[j])[2 * off[j]]     = __floats2half2_rn(v[j].x, v[j].y);
        ((__half2*)d[j])[2 * off[j] + 1] = __floats2half2_rn(v[j].z, v[j].w);
    }
}

// =====================================================================
// GEMM: C[M,N] = A[M,K] * B[N,K]^T, fp16 in, fp32 accum.
// CTA 128x128, BK=64, 256 thr (8 warps, warp tile 32x64), 3-stage cp.async,
// single __syncthreads per iteration, pitch 144B (conflict-free ldmatrix).
// =====================================================================
#define TILE144 (128 * 144)

// fused epilogues (all write single fp16 tensor):
//  EPI 0: rope + ATT_SCALE (Q)
//  EPI 1: rope (K)
//  EPI 2: plain (V)
template <int EPI>
__device__ __forceinline__ void epilogue16(
    float acc[2][8][4], __half* Ch,
    const float* cosb, const float* sinb,
    int bm, int bn, int wm, int wn, int lane, int N)
{
#pragma unroll
    for (int mt = 0; mt < 2; mt++) {
        int r0 = bm + wm + mt * 16 + (lane >> 2);
        int n0 = r0 & (NSEQ - 1);
#pragma unroll
        for (int nt = 0; nt < 8; nt++) {
            int c0 = bn + wn + nt * 8 + (lane & 3) * 2;
            float* p = acc[mt][nt];
            float p0 = p[0], p1 = p[1], p2 = p[2], p3 = p[3];
            if (EPI <= 1) {
                int j = (c0 & (HDIM - 1)) >> 1;
                float ca = cosb[n0 * 64 + j],       sa = sinb[n0 * 64 + j];
                float cb = cosb[(n0 + 8) * 64 + j], sb = sinb[(n0 + 8) * 64 + j];
                float t0 = p0 * ca - p1 * sa, t1 = p0 * sa + p1 * ca;
                float t2 = p2 * cb - p3 * sb, t3 = p2 * sb + p3 * cb;
                p0 = t0; p1 = t1; p2 = t2; p3 = t3;
            }
            if (EPI == 0) {
                p0 *= ATT_SCALE; p1 *= ATT_SCALE; p2 *= ATT_SCALE; p3 *= ATT_SCALE;
            }
            *(__half2*)&Ch[(size_t)r0 * N + c0]       = __floats2half2_rn(p0, p1);
            *(__half2*)&Ch[(size_t)(r0 + 8) * N + c0] = __floats2half2_rn(p2, p3);
        }
    }
}

// ---------------- fused QKV projection: one GEMM, per-CTA epilogue dispatch ----------------
#define G1STAGE (2 * TILE144)        // 36864
#define G1SMEM  (3 * G1STAGE)        // 110592
__global__ __launch_bounds__(256, 2) void gemm_qkv(
    const __half* __restrict__ A, const __half* __restrict__ B,
    __half* __restrict__ Qd, __half* __restrict__ Kd, __half* __restrict__ Vd,
    const float* __restrict__ cosb, const float* __restrict__ sinb, int K)
{
    extern __shared__ char smraw[];
    const uint32_t sbase = s2u32(smraw);
    const int tid  = threadIdx.x;
    const int wid  = tid >> 5;
    const int lane = tid & 31;
    const int bm = blockIdx.y << 7, bn = blockIdx.x << 7;
    const int wm = (wid & 3) * 32;
    const int wn = (wid >> 2) * 64;
    const int NCH = K >> 6;

    float acc[2][8][4];
#pragma unroll
    for (int i = 0; i < 2; i++)
#pragma unroll
        for (int j = 0; j < 8; j++)
#pragma unroll
            for (int t = 0; t < 4; t++) acc[i][j][t] = 0.0f;

    auto load_stage = [&](int ch, int st) {
        const int k0 = ch << 6;
        const uint32_t stb = sbase + st * G1STAGE;
#pragma unroll
        for (int i = 0; i < 8; i++) {
            int f = i * 256 + tid;
            int tile = f >> 10;
            int c = f & 1023;
            int row = c >> 3, ch8 = c & 7;
            const __half* g = tile ? B : A;
            int rb = tile ? bn : bm;
            cp16(stb + tile * TILE144 + row * 144 + ch8 * 16,
                 g + (size_t)(rb + row) * K + k0 + ch8 * 8);
        }
    };

    uint32_t offA[2], offB[4];
#pragma unroll
    for (int mt = 0; mt < 2; mt++)
        offA[mt] = (uint32_t)((wm + mt * 16 + (lane & 15)) * 144 + (lane >> 4) * 16);
#pragma unroll
    for (int nb = 0; nb < 4; nb++)
        offB[nb] = (uint32_t)((wn + nb * 16 + (lane & 15)) * 144 + (lane >> 4) * 16);

    load_stage(0, 0); cp_commit();
    load_stage(1, 1); cp_commit();

    for (int it = 0; it < NCH; ++it) {
        if (it + 1 < NCH) cp_wait<1>(); else cp_wait<0>();
        __syncthreads();
        if (it + 2 < NCH) { load_stage(it + 2, (it + 2) % 3); cp_commit(); }

        const uint32_t bA = sbase + (it % 3) * G1STAGE;
        const uint32_t bB = bA + TILE144;

#pragma unroll
        for (int kk = 0; kk < 4; kk++) {
            const uint32_t ks = kk * 32;
            uint32_t a[2][4], bfr[4][4];
#pragma unroll
            for (int mt = 0; mt < 2; mt++)
                ldsm4(a[mt][0], a[mt][1], a[mt][2], a[mt][3], bA + offA[mt] + ks);
#pragma unroll
            for (int nb = 0; nb < 4; nb++)
                ldsm4(bfr[nb][0], bfr[nb][1], bfr[nb][2], bfr[nb][3], bB + offB[nb] + ks);
#pragma unroll
            for (int mt = 0; mt < 2; mt++)
#pragma unroll
                for (int nb = 0; nb < 4; nb++)
#pragma unroll
                    for (int hf = 0; hf < 2; hf++)
                        mma16816f(acc[mt][nb * 2 + hf], a[mt],
                                  bfr[nb][hf], bfr[nb][hf + 2]);
        }
    }

    if (bn < DIMM) {
        epilogue16<0>(acc, Qd, cosb, sinb, bm, bn, wm, wn, lane, DIMM);
    } else if (bn < DIMM + KVDIM) {
        epilogue16<1>(acc, Kd, cosb, sinb, bm, bn - DIMM, wm, wn, lane, KVDIM);
    } else {
        epilogue16<2>(acc, Vd, cosb, sinb, bm, bn - DIMM - KVDIM, wm, wn, lane, KVDIM);
    }
}

// ---------------- 1-pass fp16 -> fp32 out: O projection ----------------
__global__ __launch_bounds__(256, 2) void gemm1p(
    const __half* __restrict__ A, const __half* __restrict__ B,
    float* __restrict__ C, int N, int K)
{
    extern __shared__ char smraw[];
    const uint32_t sbase = s2u32(smraw);
    const int tid  = threadIdx.x;
    const int wid  = tid >> 5;
    const int lane = tid & 31;
    const int bm = blockIdx.y << 7, bn = blockIdx.x << 7;
    const int wm = (wid & 3) * 32;
    const int wn = (wid >> 2) * 64;
    const int NCH = K >> 6;

    float acc[2][8][4];
#pragma unroll
    for (int i = 0; i < 2; i++)
#pragma unroll
        for (int j = 0; j < 8; j++)
#pragma unroll
            for (int t = 0; t < 4; t++) acc[i][j][t] = 0.0f;

    auto load_stage = [&](int ch, int st) {
        const int k0 = ch << 6;
        const uint32_t stb = sbase + st * G1STAGE;
#pragma unroll
        for (int i = 0; i < 8; i++) {
            int f = i * 256 + tid;
            int tile = f >> 10;
            int c = f & 1023;
            int row = c >> 3, ch8 = c & 7;
            const __half* g = tile ? B : A;
            int rb = tile ? bn : bm;
            cp16(stb + tile * TILE144 + row * 144 + ch8 * 16,
                 g + (size_t)(rb + row) * K + k0 + ch8 * 8);
        }
    };

    uint32_t offA[2], offB[4];
#pragma unroll
    for (int mt = 0; mt < 2; mt++)
        offA[mt] = (uint32_t)((wm + mt * 16 + (lane & 15)) * 144 + (lane >> 4) * 16);
#pragma unroll
    for (int nb = 0; nb < 4; nb++)
        offB[nb] = (uint32_t)((wn + nb * 16 + (lane & 15)) * 144 + (lane >> 4) * 16);

    load_stage(0, 0); cp_commit();
    load_stage(1, 1); cp_commit();

    for (int it = 0; it < NCH; ++it) {
        if (it + 1 < NCH) cp_wait<1>(); else cp_wait<0>();
        __syncthreads();
        if (it + 2 < NCH) { load_stage(it + 2, (it + 2) % 3); cp_commit(); }

        const uint32_t bA = sbase + (it % 3) * G1STAGE;
        const uint32_t bB = bA + TILE144;

#pragma unroll
        for (int kk = 0; kk < 4; kk++) {
            const uint32_t ks = kk * 32;
            uint32_t a[2][4], bfr[4][4];
#pragma unroll
            for (int mt = 0; mt < 2; mt++)
                ldsm4(a[mt][0], a[mt][1], a[mt][2], a[mt][3], bA + offA[mt] + ks);
#pragma unroll
            for (int nb = 0; nb < 4; nb++)
                ldsm4(bfr[nb][0], bfr[nb][1], bfr[nb][2], bfr[nb][3], bB + offB[nb] + ks);
#pragma unroll
            for (int mt = 0; mt < 2; mt++)
#pragma unroll
                for (int nb = 0; nb < 4; nb++)
#pragma unroll
                    for (int hf = 0; hf < 2; hf++)
                        mma16816f(acc[mt][nb * 2 + hf], a[mt],
                                  bfr[nb][hf], bfr[nb][hf + 2]);
        }
    }

#pragma unroll
    for (int mt = 0; mt < 2; mt++) {
        int r0 = bm + wm + mt * 16 + (lane >> 2);
#pragma unroll
        for (int nt = 0; nt < 8; nt++) {
            int c0 = bn + wn + nt * 8 + (lane & 3) * 2;
            float* p = acc[mt][nt];
            *(float2*)&C[(size_t)r0 * N + c0]       = make_float2(p[0], p[1]);
            *(float2*)&C[(size_t)(r0 + 8) * N + c0] = make_float2(p[2], p[3]);
        }
    }
}

// ---------------- flash attention via mma.sync ----------------
// 128 q-rows/CTA, 8 warps x 16 rows, 64-key tiles double buffered.
// S: Q fp16 single-pass vs K fp16; PV: fp16 single pass. fp32 softmax/accum.
#define APITCH  272
#define QS_BYTES (128 * APITCH)            // 34816
#define KVTILE   (64 * APITCH)             // 17408
#define STG      (2 * KVTILE)              // 34816 (K, V)
#define ASMEM    (QS_BYTES + 2 * STG)      // 104448
__global__ __launch_bounds__(256) void attn_mma(
    const __half* __restrict__ Qd, const __half* __restrict__ Kk,
    const __half* __restrict__ V, __half* __restrict__ O16)
{
    extern __shared__ char smraw[];
    const uint32_t sb = s2u32(smraw);
    const uint32_t q_s  = sb;
    const uint32_t kvb  = sb + QS_BYTES;

    const int tid = threadIdx.x;
    const int wid = tid >> 5, lane = tid & 31;
    const int qt = gridDim.x - 1 - blockIdx.x;   // big tiles first
    const int bh = blockIdx.y;
    const int b = bh >> 5, h = bh & 31;
    const int kvh = h >> 2;

    {
        const size_t qrow0 = (size_t)(b * NSEQ + qt * 128) * DIMM + h * HDIM;
#pragma unroll
        for (int i = 0; i < 8; i++) {
            int f = i * 256 + tid;           // 0..2047 16B chunks
            int row = f >> 4, ch = f & 15;
            cp16(q_s + row * APITCH + ch * 16,
                 Qd + qrow0 + (size_t)row * DIMM + ch * 8);
        }
    }

    auto load_kv = [&](int kt, int st) {
        const uint32_t stb = kvb + st * STG;
        const size_t row0 = (size_t)(b * NSEQ + kt * 64) * KVDIM + kvh * HDIM;
#pragma unroll
        for (int i = 0; i < 8; i++) {
            int f = i * 256 + tid;
            int tile = f >> 10;
            int c = f & 1023;
            int row = c >> 4, ch = c & 15;
            const __half* src = (tile ? V : Kk) + row0 + (size_t)row * KVDIM + ch * 8;
            cp16(stb + tile * KVTILE + row * APITCH + ch * 16, src);
        }
    };

    float o[16][4];
#pragma unroll
    for (int t = 0; t < 16; t++)
#pragma unroll
        for (int r = 0; r < 4; r++) o[t][r] = 0.0f;
    float m0 = -1e30f, m1 = -1e30f, l0 = 0.0f, l1 = 0.0f;

    const int NIT = 2 * qt + 2;
    load_kv(0, 0); cp_commit();

    const int rowA = qt * 128 + wid * 16 + (lane >> 2);
    const uint32_t aoff = (uint32_t)((wid * 16 + (lane & 15)) * APITCH + (lane >> 4) * 16);

    for (int it = 0; it < NIT; it++) {
        const int st = it & 1;
        cp_wait<0>();
        __syncthreads();
        if (it + 1 < NIT) { load_kv(it + 1, st ^ 1); cp_commit(); }

        const uint32_t k_t = kvb + st * STG;
        const uint32_t v_t = k_t + KVTILE;

        float s[8][4];
#pragma unroll
        for (int t = 0; t < 8; t++)
#pragma unroll
            for (int r = 0; r < 4; r++) s[t][r] = 0.0f;

#pragma unroll
        for (int kki = 0; kki < 8; kki++) {
            uint32_t a[4];
            ldsm4(a[0], a[1], a[2], a[3], q_s + aoff + kki * 32);
#pragma unroll
            for (int g = 0; g < 4; g++) {
                uint32_t boff = (uint32_t)((16 * g + (lane & 15)) * APITCH
                                           + (kki * 2 + (lane >> 4)) * 16);
                uint32_t b0, b1, b2, b3;
                ldsm4(b0, b1, b2, b3, k_t + boff);
                mma16816f(s[2 * g],     a, b0, b2);
                mma16816f(s[2 * g + 1], a, b1, b3);
            }
        }

        if (it >= 2 * qt) {
            const int kbase = it * 64 + (lane & 3) * 2;
#pragma unroll
            for (int t = 0; t < 8; t++) {
                int k0 = kbase + t * 8;
                if (k0     > rowA)     s[t][0] = -1e30f;
                if (k0 + 1 > rowA)     s[t][1] = -1e30f;
                if (k0     > rowA + 8) s[t][2] = -1e30f;
                if (k0 + 1 > rowA + 8) s[t][3] = -1e30f;
            }
        }

        float mxA = m0, mxB = m1;
#pragma unroll
        for (int t = 0; t < 8; t++) {
            mxA = fmaxf(mxA, fmaxf(s[t][0], s[t][1]));
            mxB = fmaxf(mxB, fmaxf(s[t][2], s[t][3]));
        }
        mxA = fmaxf(mxA, __shfl_xor_sync(0xFFFFFFFFu, mxA, 1));
        mxA = fmaxf(mxA, __shfl_xor_sync(0xFFFFFFFFu, mxA, 2));
        mxB = fmaxf(mxB, __shfl_xor_sync(0xFFFFFFFFu, mxB, 1));
        mxB = fmaxf(mxB, __shfl_xor_sync(0xFFFFFFFFu, mxB, 2));

        float aA = __expf(m0 - mxA), aB = __expf(m1 - mxB);
        float sA = 0.0f, sB = 0.0f;
#pragma unroll
        for (int t = 0; t < 8; t++) {
            s[t][0] = __expf(s[t][0] - mxA);
            s[t][1] = __expf(s[t][1] - mxA);
            s[t][2] = __expf(s[t][2] - mxB);
            s[t][3] = __expf(s[t][3] - mxB);
            sA += s[t][0] + s[t][1];
            sB += s[t][2] + s[t][3];
        }
        sA += __shfl_xor_sync(0xFFFFFFFFu, sA, 1);
        sA += __shfl_xor_sync(0xFFFFFFFFu, sA, 2);
        sB += __shfl_xor_sync(0xFFFFFFFFu, sB, 1);
        sB += __shfl_xor_sync(0xFFFFFFFFu, sB, 2);
        l0 = l0 * aA + sA;  l1 = l1 * aB + sB;
        m0 = mxA;           m1 = mxB;

#pragma unroll
        for (int t = 0; t < 16; t++) {
            o[t][0] *= aA; o[t][1] *= aA;
            o[t][2] *= aB; o[t][3] *= aB;
        }

        uint32_t ap[4][4];
#pragma unroll
        for (int kk = 0; kk < 4; kk++) {
            ap[kk][0] = packh2(s[2 * kk][0],     s[2 * kk][1]);
            ap[kk][1] = packh2(s[2 * kk][2],     s[2 * kk][3]);
            ap[kk][2] = packh2(s[2 * kk + 1][0], s[2 * kk + 1][1]);
            ap[kk][3] = packh2(s[2 * kk + 1][2], s[2 * kk + 1][3]);
        }
        const uint32_t vrow = (uint32_t)((((lane >> 3) & 1) * 8 + (lane & 7)) * APITCH
                                         + (lane >> 4) * 16);
#pragma unroll
        for (int kk = 0; kk < 4; kk++) {
#pragma unroll
            for (int g = 0; g < 8; g++) {
                uint32_t v0, v1, v2, v3;
                ldsm4t(v0, v1, v2, v3, v_t + vrow + (uint32_t)(16 * kk * APITCH + g * 32));
                mma16816f(o[2 * g],     ap[kk], v0, v1);
                mma16816f(o[2 * g + 1], ap[kk], v2, v3);
            }
        }
    }

    const float iA = 1.0f / l0, iB = 1.0f / l1;
    __half* obase = O16 + ((size_t)(b * NSEQ) * NHEAD + h) * HDIM;
#pragma unroll
    for (int t = 0; t < 16; t++) {
        int d = t * 8 + (lane & 3) * 2;
        *(__half2*)(obase + (size_t)rowA * (NHEAD * HDIM) + d) =
            __floats2half2_rn(o[t][0] * iA, o[t][1] * iA);
        *(__half2*)(obase + (size_t)(rowA + 8) * (NHEAD * HDIM) + d) =
            __floats2half2_rn(o[t][2] * iB, o[t][3] * iB);
    }
}

// ---------------- launch ----------------
extern "C" void kernel_launch(void* const* d_in, const int* in_sizes, int n_in,
                              void* d_out, int out_size)
{
    const float* x    = (const float*)d_in[0];
    const float* wq   = (const float*)d_in[1];
    const float* wk   = (const float*)d_in[2];
    const float* wv   = (const float*)d_in[3];
    const float* wo   = (const float*)d_in[4];
    const float* cosb = (const float*)d_in[5];
    const float* sinb = (const float*)d_in[6];
    float* out = (float*)d_out;

    __half *x16, *wqkv16, *wo16;
    cudaGetSymbolAddress((void**)&x16,    g_x16);
    cudaGetSymbolAddress((void**)&wqkv16, g_wqkv16);
    cudaGetSymbolAddress((void**)&wo16,   g_wo16);
    __half *q16, *k16, *v16, *o16;
    cudaGetSymbolAddress((void**)&q16, g_q16);
    cudaGetSymbolAddress((void**)&k16, g_k16);
    cudaGetSymbolAddress((void**)&v16, g_v16);
    cudaGetSymbolAddress((void**)&o16, g_o16);

    cudaFuncSetAttribute(gemm_qkv, cudaFuncAttributeMaxDynamicSharedMemorySize, G1SMEM);
    cudaFuncSetAttribute(gemm1p,   cudaFuncAttributeMaxDynamicSharedMemorySize, G1SMEM);
    cudaFuncSetAttribute(attn_mma, cudaFuncAttributeMaxDynamicSharedMemorySize, ASMEM);

    dim3 blk(256);

    // all fp32 -> fp16 conversions in one launch, MLP=4
    cvt_all_kernel<<<CVT_GRID, blk>>>(x, wq, wk, wv, wo, x16, wqkv16, wo16);

    // fused QKV projection (rope/scale epilogues dispatched per CTA)
    gemm_qkv<<<dim3(NQKV / 128, MROWS / 128), blk, G1SMEM>>>(
        x16, wqkv16, q16, k16, v16, cosb, sinb, DIMM);

    // attention (Q/K/V fp16, single-pass S) -> fp16 o16
    attn_mma<<<dim3(NSEQ / 128, BATCH * NHEAD), blk, ASMEM>>>(q16, k16, v16, o16);

    // output projection: single-pass fp16, fp32 out
    gemm1p<<<dim3(DIMM / 128, MROWS / 128), blk, G1SMEM>>>(o16, wo16, out, DIMM, DIMM);
}